// round 2
// baseline (speedup 1.0000x reference)
#include <cuda_runtime.h>
#include <math.h>

#define NTOK 81920
#define DMODEL 512
#define DFF 2048
#define NH 8
#define HD 64
#define CTXT 20
#define NB 4096
#define QKVC 1536

// ---------------- scratch (static device allocations; no cudaMalloc) ----------------
__device__ float g_h[(size_t)NTOK * DMODEL];      // LN output (reused for h2)
__device__ float g_qkv[(size_t)NTOK * QKVC];      // [N, 1536] = [q|k|v], col h*64+e
__device__ float g_ctx[(size_t)NTOK * DMODEL];    // attention context, concat heads
__device__ float g_x2[(size_t)NTOK * DMODEL];     // x + attn_out
__device__ float g_u[(size_t)NTOK * DFF];         // FFN hidden
__device__ float g_wqkv[DMODEL * QKVC];           // packed [D, 1536]
__device__ float g_woT[DMODEL * DMODEL];          // Wo transposed -> [D, D]

// ---------------- weight packing ----------------
__global__ void pack_weights(const float* __restrict__ Wq, const float* __restrict__ Wk,
                             const float* __restrict__ Wv, const float* __restrict__ Wo,
                             float* __restrict__ wqkv, float* __restrict__ woT) {
    int i = blockIdx.x * blockDim.x + threadIdx.x;
    if (i >= DMODEL * DMODEL) return;
    int d = i / DMODEL;
    int hj = i % DMODEL;          // h*64 + e
    int h = hj / HD, e = hj % HD;
    size_t widx = (size_t)h * DMODEL * HD + (size_t)d * HD + e;
    wqkv[(size_t)d * QKVC + hj]          = Wq[widx];
    wqkv[(size_t)d * QKVC + 512 + hj]    = Wk[widx];
    wqkv[(size_t)d * QKVC + 1024 + hj]   = Wv[widx];
    woT[(size_t)d * DMODEL + hj] = Wo[(size_t)hj * DMODEL + d];
}

// ---------------- layernorm: one warp per token ----------------
__global__ void ln_kernel(const float* __restrict__ x, const float* __restrict__ w,
                          const float* __restrict__ b, float* __restrict__ out) {
    int gw = (blockIdx.x * blockDim.x + threadIdx.x) >> 5;
    int lane = threadIdx.x & 31;
    if (gw >= NTOK) return;
    const float4* xp = (const float4*)(x + (size_t)gw * DMODEL);
    float4 v[4];
    float s = 0.f, s2 = 0.f;
#pragma unroll
    for (int i = 0; i < 4; i++) {
        v[i] = xp[lane + 32 * i];
        s  += v[i].x + v[i].y + v[i].z + v[i].w;
        s2 += v[i].x * v[i].x + v[i].y * v[i].y + v[i].z * v[i].z + v[i].w * v[i].w;
    }
#pragma unroll
    for (int o = 16; o > 0; o >>= 1) {
        s  += __shfl_xor_sync(0xffffffffu, s,  o);
        s2 += __shfl_xor_sync(0xffffffffu, s2, o);
    }
    float mean = s * (1.f / DMODEL);
    float var  = s2 * (1.f / DMODEL) - mean * mean;
    float rs = rsqrtf(var + 1e-5f);
    float4* op = (float4*)(out + (size_t)gw * DMODEL);
    const float4* wp = (const float4*)w;
    const float4* bp = (const float4*)b;
#pragma unroll
    for (int i = 0; i < 4; i++) {
        int idx = lane + 32 * i;
        float4 wv = wp[idx], bv = bp[idx], r;
        r.x = (v[i].x - mean) * rs * wv.x + bv.x;
        r.y = (v[i].y - mean) * rs * wv.y + bv.y;
        r.z = (v[i].z - mean) * rs * wv.z + bv.z;
        r.w = (v[i].w - mean) * rs * wv.w + bv.w;
        op[idx] = r;
    }
}

// ---------------- attention: one warp per (b,h); lane t holds q row + output row ----------------
__global__ void attn_kernel(const float* __restrict__ qkv, float* __restrict__ ctx) {
    __shared__ float Ks[4][CTXT * HD];
    __shared__ float Vs[4][CTXT * HD];
    int warp = threadIdx.x >> 5, lane = threadIdx.x & 31;
    int pair = blockIdx.x * 4 + warp;           // 0 .. B*H-1
    int b = pair >> 3, h = pair & 7;
    const float* base = qkv + (size_t)b * CTXT * QKVC + h * HD;
    // cooperative K,V load into smem
    for (int i = lane; i < CTXT * (HD / 4); i += 32) {
        int t = i >> 4, c = (i & 15) << 2;
        float4 kk = *(const float4*)(base + (size_t)t * QKVC + 512 + c);
        float4 vv = *(const float4*)(base + (size_t)t * QKVC + 1024 + c);
        *(float4*)&Ks[warp][t * HD + c] = kk;
        *(float4*)&Vs[warp][t * HD + c] = vv;
    }
    __syncwarp();

    float q[HD];
    int t = lane;
    if (t < CTXT) {
#pragma unroll
        for (int c = 0; c < HD; c += 4) {
            float4 qq = *(const float4*)(base + (size_t)t * QKVC + c);
            q[c] = qq.x; q[c + 1] = qq.y; q[c + 2] = qq.z; q[c + 3] = qq.w;
        }
    } else {
#pragma unroll
        for (int c = 0; c < HD; c++) q[c] = 0.f;
    }

    float S[CTXT];
#pragma unroll
    for (int s = 0; s < CTXT; s++) {
        float acc = 0.f;
#pragma unroll
        for (int c = 0; c < HD; c++) acc = fmaf(q[c], Ks[warp][s * HD + c], acc);
        S[s] = (s <= t) ? acc * 0.125f : -1e30f;
    }
    float m = -1e30f;
#pragma unroll
    for (int s = 0; s < CTXT; s++) m = fmaxf(m, S[s]);
    float sum = 0.f;
#pragma unroll
    for (int s = 0; s < CTXT; s++) { S[s] = __expf(S[s] - m); sum += S[s]; }
    float inv = 1.f / sum;

    float o[HD];
#pragma unroll
    for (int c = 0; c < HD; c++) o[c] = 0.f;
#pragma unroll
    for (int s = 0; s < CTXT; s++) {
        float p = S[s] * inv;
#pragma unroll
        for (int c = 0; c < HD; c++) o[c] = fmaf(p, Vs[warp][s * HD + c], o[c]);
    }
    if (t < CTXT) {
        float* dst = ctx + (size_t)(b * CTXT + t) * DMODEL + h * HD;
#pragma unroll
        for (int c = 0; c < HD; c += 4) {
            float4 ov = make_float4(o[c], o[c + 1], o[c + 2], o[c + 3]);
            *(float4*)(dst + c) = ov;
        }
    }
}

// ---------------- SGEMM 128x128x8, 256 threads, 8x8 microtile; fused epilogue ----------------
template <bool RELU>
__global__ void __launch_bounds__(256, 2)
sgemm(const float* __restrict__ A, const float* __restrict__ B,
      const float* __restrict__ bias, const float* __restrict__ res,
      float* __restrict__ C, int M, int Nn, int K) {
    __shared__ float As[8][128];
    __shared__ float Bs[8][128];
    int tid = threadIdx.x;
    int row0 = blockIdx.y * 128, col0 = blockIdx.x * 128;
    int arow = tid >> 1, acol = (tid & 1) << 2;
    int brow = tid >> 5, bcol = (tid & 31) << 2;
    int trow = (tid >> 4) << 3, tcol = (tid & 15) << 3;

    float acc[8][8];
#pragma unroll
    for (int i = 0; i < 8; i++)
#pragma unroll
        for (int j = 0; j < 8; j++) acc[i][j] = 0.f;

    const float* Aptr = A + (size_t)(row0 + arow) * K + acol;
    const float* Bptr = B + (size_t)brow * Nn + col0 + bcol;

    for (int k0 = 0; k0 < K; k0 += 8) {
        float4 av = *(const float4*)(Aptr + k0);
        float4 bv = *(const float4*)(Bptr + (size_t)k0 * Nn);
        __syncthreads();
        As[acol + 0][arow] = av.x;
        As[acol + 1][arow] = av.y;
        As[acol + 2][arow] = av.z;
        As[acol + 3][arow] = av.w;
        *(float4*)&Bs[brow][bcol] = bv;
        __syncthreads();
#pragma unroll
        for (int k = 0; k < 8; k++) {
            float a[8], bb[8];
            *(float4*)(a)      = *(const float4*)&As[k][trow];
            *(float4*)(a + 4)  = *(const float4*)&As[k][trow + 4];
            *(float4*)(bb)     = *(const float4*)&Bs[k][tcol];
            *(float4*)(bb + 4) = *(const float4*)&Bs[k][tcol + 4];
#pragma unroll
            for (int i = 0; i < 8; i++)
#pragma unroll
                for (int j = 0; j < 8; j++)
                    acc[i][j] = fmaf(a[i], bb[j], acc[i][j]);
        }
    }

#pragma unroll
    for (int i = 0; i < 8; i++) {
        size_t roff = (size_t)(row0 + trow + i) * Nn + col0 + tcol;
#pragma unroll
        for (int j = 0; j < 8; j += 4) {
            float4 vv = make_float4(acc[i][j], acc[i][j + 1], acc[i][j + 2], acc[i][j + 3]);
            if (bias) {
                float4 bb = *(const float4*)(bias + col0 + tcol + j);
                vv.x += bb.x; vv.y += bb.y; vv.z += bb.z; vv.w += bb.w;
            }
            if (RELU) {
                vv.x = fmaxf(vv.x, 0.f); vv.y = fmaxf(vv.y, 0.f);
                vv.z = fmaxf(vv.z, 0.f); vv.w = fmaxf(vv.w, 0.f);
            }
            if (res) {
                float4 rr = *(const float4*)(res + roff + j);
                vv.x += rr.x; vv.y += rr.y; vv.z += rr.z; vv.w += rr.w;
            }
            *(float4*)(C + roff + j) = vv;
        }
    }
}

// ---------------- launcher ----------------
extern "C" void kernel_launch(void* const* d_in, const int* in_sizes, int n_in,
                              void* d_out, int out_size) {
    const float* x     = (const float*)d_in[0];
    const float* ln1_w = (const float*)d_in[1];
    const float* ln1_b = (const float*)d_in[2];
    const float* Wq    = (const float*)d_in[3];
    const float* Wk    = (const float*)d_in[4];
    const float* Wv    = (const float*)d_in[5];
    const float* Wo    = (const float*)d_in[6];
    const float* Wo_b  = (const float*)d_in[7];
    const float* ln2_w = (const float*)d_in[8];
    const float* ln2_b = (const float*)d_in[9];
    const float* W1    = (const float*)d_in[10];
    const float* b1    = (const float*)d_in[11];
    const float* W2    = (const float*)d_in[12];
    const float* b2    = (const float*)d_in[13];
    float* out = (float*)d_out;

    float *h, *qkv, *ctx, *x2, *u, *wqkv, *woT;
    cudaGetSymbolAddress((void**)&h,    g_h);
    cudaGetSymbolAddress((void**)&qkv,  g_qkv);
    cudaGetSymbolAddress((void**)&ctx,  g_ctx);
    cudaGetSymbolAddress((void**)&x2,   g_x2);
    cudaGetSymbolAddress((void**)&u,    g_u);
    cudaGetSymbolAddress((void**)&wqkv, g_wqkv);
    cudaGetSymbolAddress((void**)&woT,  g_woT);

    // 1) pack weights
    pack_weights<<<(DMODEL * DMODEL + 255) / 256, 256>>>(Wq, Wk, Wv, Wo, wqkv, woT);
    // 2) h = LN1(x)
    ln_kernel<<<NTOK / 8, 256>>>(x, ln1_w, ln1_b, h);
    // 3) qkv = h @ Wqkv  [N,1536]
    sgemm<false><<<dim3(QKVC / 128, NTOK / 128), 256>>>(h, wqkv, nullptr, nullptr, qkv,
                                                        NTOK, QKVC, DMODEL);
    // 4) attention -> ctx [N,512]
    attn_kernel<<<(NB * NH) / 4, 128>>>(qkv, ctx);
    // 5) x2 = x + ctx @ Wo^T + Wo_b
    sgemm<false><<<dim3(DMODEL / 128, NTOK / 128), 256>>>(ctx, woT, Wo_b, x, x2,
                                                          NTOK, DMODEL, DMODEL);
    // 6) h2 = LN2(x2) (reuse h)
    ln_kernel<<<NTOK / 8, 256>>>(x2, ln2_w, ln2_b, h);
    // 7) u = relu(h2 @ W1 + b1)
    sgemm<true><<<dim3(DFF / 128, NTOK / 128), 256>>>(h, W1, b1, nullptr, u,
                                                      NTOK, DFF, DMODEL);
    // 8) out = x2 + u @ W2 + b2
    sgemm<false><<<dim3(DMODEL / 128, NTOK / 128), 256>>>(u, W2, b2, x2, out,
                                                          NTOK, DMODEL, DFF);
}

// round 5
// speedup vs baseline: 3.0878x; 3.0878x over previous
#include <cuda_runtime.h>
#include <cuda_bf16.h>
#include <cstdint>
#include <math.h>

#define NTOK 81920
#define DMODEL 512
#define DFF 2048
#define NH 8
#define HD 64
#define CTXT 20
#define NB 4096
#define QKVC 1536

// ---------------- scratch ----------------
__device__ float g_qkv[(size_t)NTOK * QKVC];
__device__ float g_x2[(size_t)NTOK * DMODEL];
__device__ __nv_bfloat16 g_hh[(size_t)NTOK * DMODEL], g_hl[(size_t)NTOK * DMODEL];
__device__ __nv_bfloat16 g_ch[(size_t)NTOK * DMODEL], g_cl[(size_t)NTOK * DMODEL];
__device__ __nv_bfloat16 g_uh[(size_t)NTOK * DFF],    g_ul[(size_t)NTOK * DFF];
// packed weights: [N][K] bf16 hi/lo
__device__ __nv_bfloat16 g_bqkv_hi[QKVC * DMODEL], g_bqkv_lo[QKVC * DMODEL];
__device__ __nv_bfloat16 g_bo_hi[DMODEL * DMODEL], g_bo_lo[DMODEL * DMODEL];
__device__ __nv_bfloat16 g_b1_hi[DFF * DMODEL],    g_b1_lo[DFF * DMODEL];
__device__ __nv_bfloat16 g_b2_hi[DMODEL * DFF],    g_b2_lo[DMODEL * DFF];

// ---------------- helpers ----------------
__device__ __forceinline__ uint32_t smem_to_u32(const void* p) {
    uint32_t a;
    asm("{ .reg .u64 t; cvta.to.shared.u64 t, %1; cvt.u32.u64 %0, t; }" : "=r"(a) : "l"(p));
    return a;
}
#define CP_ASYNC16(dst, src) \
    asm volatile("cp.async.cg.shared.global [%0], [%1], 16;" :: "r"(dst), "l"(src))
#define CP_COMMIT() asm volatile("cp.async.commit_group;")
#define CP_WAIT1()  asm volatile("cp.async.wait_group 1;")

__device__ __forceinline__ void ldsm4(uint32_t& r0, uint32_t& r1, uint32_t& r2, uint32_t& r3,
                                      uint32_t addr) {
    asm volatile("ldmatrix.sync.aligned.m8n8.x4.shared.b16 {%0,%1,%2,%3}, [%4];"
                 : "=r"(r0), "=r"(r1), "=r"(r2), "=r"(r3) : "r"(addr));
}
__device__ __forceinline__ void mma16816(float* c, uint32_t a0, uint32_t a1, uint32_t a2,
                                         uint32_t a3, uint32_t b0, uint32_t b1) {
    asm volatile(
        "mma.sync.aligned.m16n8k16.row.col.f32.bf16.bf16.f32 "
        "{%0,%1,%2,%3}, {%4,%5,%6,%7}, {%8,%9}, {%0,%1,%2,%3};"
        : "+f"(c[0]), "+f"(c[1]), "+f"(c[2]), "+f"(c[3])
        : "r"(a0), "r"(a1), "r"(a2), "r"(a3), "r"(b0), "r"(b1));
}

// ---------------- weight packing ----------------
__global__ void pack_qkv_bf(const float* __restrict__ Wq, const float* __restrict__ Wk,
                            const float* __restrict__ Wv,
                            __nv_bfloat16* __restrict__ hi, __nv_bfloat16* __restrict__ lo) {
    int i = blockIdx.x * blockDim.x + threadIdx.x;
    if (i >= QKVC * DMODEL) return;
    int n = i >> 9, k = i & 511;
    int sec = n >> 9, h = (n >> 6) & 7, e = n & 63;
    const float* W = (sec == 0) ? Wq : (sec == 1 ? Wk : Wv);
    float v = W[((size_t)h * DMODEL + k) * HD + e];
    __nv_bfloat16 hh = __float2bfloat16(v);
    hi[i] = hh;
    lo[i] = __float2bfloat16(v - __bfloat162float(hh));
}
__global__ void pack_T_bf(const float* __restrict__ W, __nv_bfloat16* __restrict__ hi,
                          __nv_bfloat16* __restrict__ lo, int K, int N) {
    int i = blockIdx.x * blockDim.x + threadIdx.x;
    if (i >= K * N) return;
    int n = i / K, k = i - n * K;
    float v = W[(size_t)k * N + n];
    __nv_bfloat16 hh = __float2bfloat16(v);
    hi[i] = hh;
    lo[i] = __float2bfloat16(v - __bfloat162float(hh));
}
__global__ void pack_noT_bf(const float* __restrict__ W, __nv_bfloat16* __restrict__ hi,
                            __nv_bfloat16* __restrict__ lo, int total) {
    int i = blockIdx.x * blockDim.x + threadIdx.x;
    if (i >= total) return;
    float v = W[i];
    __nv_bfloat16 hh = __float2bfloat16(v);
    hi[i] = hh;
    lo[i] = __float2bfloat16(v - __bfloat162float(hh));
}

// ---------------- layernorm -> bf16 hi/lo ----------------
__global__ void ln_split(const float* __restrict__ x, const float* __restrict__ w,
                         const float* __restrict__ b, __nv_bfloat16* __restrict__ hi,
                         __nv_bfloat16* __restrict__ lo) {
    int gw = (blockIdx.x * blockDim.x + threadIdx.x) >> 5;
    int lane = threadIdx.x & 31;
    if (gw >= NTOK) return;
    const float4* xp = (const float4*)(x + (size_t)gw * DMODEL);
    float4 v[4];
    float s = 0.f, s2 = 0.f;
#pragma unroll
    for (int i = 0; i < 4; i++) {
        v[i] = xp[lane + 32 * i];
        s  += v[i].x + v[i].y + v[i].z + v[i].w;
        s2 += v[i].x * v[i].x + v[i].y * v[i].y + v[i].z * v[i].z + v[i].w * v[i].w;
    }
#pragma unroll
    for (int o = 16; o > 0; o >>= 1) {
        s  += __shfl_xor_sync(0xffffffffu, s,  o);
        s2 += __shfl_xor_sync(0xffffffffu, s2, o);
    }
    float mean = s * (1.f / DMODEL);
    float var  = s2 * (1.f / DMODEL) - mean * mean;
    float rs = rsqrtf(var + 1e-5f);
    const float4* wp = (const float4*)w;
    const float4* bp = (const float4*)b;
#pragma unroll
    for (int i = 0; i < 4; i++) {
        int idx = lane + 32 * i;
        float4 wv = wp[idx], bv = bp[idx], r;
        r.x = (v[i].x - mean) * rs * wv.x + bv.x;
        r.y = (v[i].y - mean) * rs * wv.y + bv.y;
        r.z = (v[i].z - mean) * rs * wv.z + bv.z;
        r.w = (v[i].w - mean) * rs * wv.w + bv.w;
        __nv_bfloat162 h01 = __floats2bfloat162_rn(r.x, r.y);
        __nv_bfloat162 h23 = __floats2bfloat162_rn(r.z, r.w);
        __nv_bfloat162 l01 = __floats2bfloat162_rn(r.x - __bfloat162float(h01.x),
                                                   r.y - __bfloat162float(h01.y));
        __nv_bfloat162 l23 = __floats2bfloat162_rn(r.z - __bfloat162float(h23.x),
                                                   r.w - __bfloat162float(h23.y));
        size_t off = (size_t)gw * DMODEL + idx * 4;
        uint2 ph, pl;
        ph.x = *reinterpret_cast<uint32_t*>(&h01);
        ph.y = *reinterpret_cast<uint32_t*>(&h23);
        pl.x = *reinterpret_cast<uint32_t*>(&l01);
        pl.y = *reinterpret_cast<uint32_t*>(&l23);
        *(uint2*)(hi + off) = ph;
        *(uint2*)(lo + off) = pl;
    }
}

// ---------------- attention -> ctx bf16 hi/lo ----------------
__global__ void attn_kernel(const float* __restrict__ qkv, __nv_bfloat16* __restrict__ chi,
                            __nv_bfloat16* __restrict__ clo) {
    __shared__ float Ks[4][CTXT * HD];
    __shared__ float Vs[4][CTXT * HD];
    int warp = threadIdx.x >> 5, lane = threadIdx.x & 31;
    int pair = blockIdx.x * 4 + warp;
    int b = pair >> 3, h = pair & 7;
    const float* base = qkv + (size_t)b * CTXT * QKVC + h * HD;
    for (int i = lane; i < CTXT * (HD / 4); i += 32) {
        int t = i >> 4, c = (i & 15) << 2;
        float4 kk = *(const float4*)(base + (size_t)t * QKVC + 512 + c);
        float4 vv = *(const float4*)(base + (size_t)t * QKVC + 1024 + c);
        *(float4*)&Ks[warp][t * HD + c] = kk;
        *(float4*)&Vs[warp][t * HD + c] = vv;
    }
    __syncwarp();
    float q[HD];
    int t = lane;
    if (t < CTXT) {
#pragma unroll
        for (int c = 0; c < HD; c += 4) {
            float4 qq = *(const float4*)(base + (size_t)t * QKVC + c);
            q[c] = qq.x; q[c + 1] = qq.y; q[c + 2] = qq.z; q[c + 3] = qq.w;
        }
    } else {
#pragma unroll
        for (int c = 0; c < HD; c++) q[c] = 0.f;
    }
    float S[CTXT];
#pragma unroll
    for (int s = 0; s < CTXT; s++) {
        float acc = 0.f;
#pragma unroll
        for (int c = 0; c < HD; c++) acc = fmaf(q[c], Ks[warp][s * HD + c], acc);
        S[s] = (s <= t) ? acc * 0.125f : -1e30f;
    }
    float m = -1e30f;
#pragma unroll
    for (int s = 0; s < CTXT; s++) m = fmaxf(m, S[s]);
    float sum = 0.f;
#pragma unroll
    for (int s = 0; s < CTXT; s++) { S[s] = __expf(S[s] - m); sum += S[s]; }
    float inv = 1.f / sum;
    float o[HD];
#pragma unroll
    for (int c = 0; c < HD; c++) o[c] = 0.f;
#pragma unroll
    for (int s = 0; s < CTXT; s++) {
        float p = S[s] * inv;
#pragma unroll
        for (int c = 0; c < HD; c++) o[c] = fmaf(p, Vs[warp][s * HD + c], o[c]);
    }
    if (t < CTXT) {
        size_t off = (size_t)(b * CTXT + t) * DMODEL + h * HD;
#pragma unroll
        for (int c = 0; c < HD; c += 4) {
            __nv_bfloat162 h01 = __floats2bfloat162_rn(o[c], o[c + 1]);
            __nv_bfloat162 h23 = __floats2bfloat162_rn(o[c + 2], o[c + 3]);
            __nv_bfloat162 l01 = __floats2bfloat162_rn(o[c] - __bfloat162float(h01.x),
                                                       o[c + 1] - __bfloat162float(h01.y));
            __nv_bfloat162 l23 = __floats2bfloat162_rn(o[c + 2] - __bfloat162float(h23.x),
                                                       o[c + 3] - __bfloat162float(h23.y));
            uint2 ph, pl;
            ph.x = *reinterpret_cast<uint32_t*>(&h01);
            ph.y = *reinterpret_cast<uint32_t*>(&h23);
            pl.x = *reinterpret_cast<uint32_t*>(&l01);
            pl.y = *reinterpret_cast<uint32_t*>(&l23);
            *(uint2*)(chi + off + c) = ph;
            *(uint2*)(clo + off + c) = pl;
        }
    }
}

// ---------------- mma.sync bf16x3 GEMM: C[M,N] = A[M,K] @ B[N,K]^T ----------------
// 128x128 CTA tile, BK=32, 3-stage cp.async, 8 warps of 64x32.
// Stage layout (32KB): Ahi[128][32] @0, Alo @8192, Bhi @16384, Blo @24576.
// Swizzle: byte = r*64 + ((c ^ ((r>>1)&3))<<4), c = 16B-chunk index 0..3.
#define GSMEM (3 * 32768)

template <int EPI>  // 0: fp32 out (+bias?,+res?);  1: relu(acc+bias) -> bf16 hi/lo out
__global__ void __launch_bounds__(256, 2)
mma_gemm(const __nv_bfloat16* __restrict__ Ahi, const __nv_bfloat16* __restrict__ Alo,
         const __nv_bfloat16* __restrict__ Bhi, const __nv_bfloat16* __restrict__ Blo,
         const float* __restrict__ bias, const float* __restrict__ res,
         float* __restrict__ C, __nv_bfloat16* __restrict__ Chi,
         __nv_bfloat16* __restrict__ Clo, int M, int N, int K) {
    extern __shared__ __align__(128) char smem[];
    uint32_t sb = smem_to_u32(smem);
    int tid = threadIdx.x, lane = tid & 31, wid = tid >> 5;
    int row0 = blockIdx.y * 128, col0 = blockIdx.x * 128;
    int wm = wid & 1, wn = wid >> 1;

    // cp.async chunk assignments (8 chunks / thread / stage)
    uint32_t dstOff[8];
    const __nv_bfloat16* gsrc[8];
#pragma unroll
    for (int it = 0; it < 8; ++it) {
        int idx = ((it & 1) << 8) + tid;        // 0..511 within region
        int r = idx >> 2, c = idx & 3;
        int region = it >> 1;                   // 0 Ahi, 1 Alo, 2 Bhi, 3 Blo
        dstOff[it] = region * 8192 + r * 64 + ((c ^ ((r >> 1) & 3)) << 4);
        const __nv_bfloat16* base = (region == 0) ? Ahi : (region == 1) ? Alo
                                   : (region == 2) ? Bhi : Blo;
        int rowg = ((region < 2) ? row0 : col0) + r;
        gsrc[it] = base + (size_t)rowg * K + c * 8;
    }

    // ldmatrix base addresses (stage 0; add stage offset per iter)
    uint32_t aB[2], bB[2];
    {
        int ra = wm * 64 + (lane & 15);
        int rb = wn * 32 + (lane & 7) + ((lane >> 4) << 3);
#pragma unroll
        for (int kc = 0; kc < 2; ++kc) {
            int ca = kc * 2 + (lane >> 4);
            aB[kc] = sb + ra * 64 + ((ca ^ ((ra >> 1) & 3)) << 4);
            int cb = kc * 2 + ((lane >> 3) & 1);
            bB[kc] = sb + 16384 + rb * 64 + ((cb ^ ((rb >> 1) & 3)) << 4);
        }
    }

    float acc[4][4][4];
#pragma unroll
    for (int i = 0; i < 4; i++)
#pragma unroll
        for (int j = 0; j < 4; j++)
#pragma unroll
            for (int k = 0; k < 4; k++) acc[i][j][k] = 0.f;

    const int T = K >> 5;
    // prologue: stages 0,1
#pragma unroll
    for (int it = 0; it < 8; ++it) CP_ASYNC16(sb + dstOff[it], gsrc[it]);
    CP_COMMIT();
#pragma unroll
    for (int it = 0; it < 8; ++it) CP_ASYNC16(sb + 32768 + dstOff[it], gsrc[it] + 32);
    CP_COMMIT();

    for (int t = 0; t < T; ++t) {
        CP_WAIT1();
        __syncthreads();
        if (t + 2 < T) {
            int s2 = (t + 2) % 3;
            size_t ko = (size_t)(t + 2) * 32;
#pragma unroll
            for (int it = 0; it < 8; ++it)
                CP_ASYNC16(sb + s2 * 32768 + dstOff[it], gsrc[it] + ko);
        }
        CP_COMMIT();

        uint32_t so = (uint32_t)(t % 3) * 32768u;
#pragma unroll
        for (int kc = 0; kc < 2; ++kc) {
            uint32_t aA = aB[kc] + so, bA = bB[kc] + so;
            uint32_t aR[16], bR[8];
            // A hi
#pragma unroll
            for (int mf = 0; mf < 4; ++mf)
                ldsm4(aR[mf * 4], aR[mf * 4 + 1], aR[mf * 4 + 2], aR[mf * 4 + 3],
                      aA + mf * 1024);
            // B hi
            ldsm4(bR[0], bR[1], bR[2], bR[3], bA);
            ldsm4(bR[4], bR[5], bR[6], bR[7], bA + 1024);
#pragma unroll
            for (int mf = 0; mf < 4; ++mf)
#pragma unroll
                for (int nf = 0; nf < 4; ++nf)
                    mma16816(acc[mf][nf], aR[mf * 4], aR[mf * 4 + 1], aR[mf * 4 + 2],
                             aR[mf * 4 + 3], bR[(nf >> 1) * 4 + (nf & 1) * 2],
                             bR[(nf >> 1) * 4 + (nf & 1) * 2 + 1]);
            // B lo (A hi still loaded)
            ldsm4(bR[0], bR[1], bR[2], bR[3], bA + 8192);
            ldsm4(bR[4], bR[5], bR[6], bR[7], bA + 8192 + 1024);
#pragma unroll
            for (int mf = 0; mf < 4; ++mf)
#pragma unroll
                for (int nf = 0; nf < 4; ++nf)
                    mma16816(acc[mf][nf], aR[mf * 4], aR[mf * 4 + 1], aR[mf * 4 + 2],
                             aR[mf * 4 + 3], bR[(nf >> 1) * 4 + (nf & 1) * 2],
                             bR[(nf >> 1) * 4 + (nf & 1) * 2 + 1]);
            // A lo x B hi
#pragma unroll
            for (int mf = 0; mf < 4; ++mf)
                ldsm4(aR[mf * 4], aR[mf * 4 + 1], aR[mf * 4 + 2], aR[mf * 4 + 3],
                      aA + 8192 + mf * 1024);
            ldsm4(bR[0], bR[1], bR[2], bR[3], bA);
            ldsm4(bR[4], bR[5], bR[6], bR[7], bA + 1024);
#pragma unroll
            for (int mf = 0; mf < 4; ++mf)
#pragma unroll
                for (int nf = 0; nf < 4; ++nf)
                    mma16816(acc[mf][nf], aR[mf * 4], aR[mf * 4 + 1], aR[mf * 4 + 2],
                             aR[mf * 4 + 3], bR[(nf >> 1) * 4 + (nf & 1) * 2],
                             bR[(nf >> 1) * 4 + (nf & 1) * 2 + 1]);
        }
    }

    // epilogue
    int m0 = row0 + wm * 64, n0 = col0 + wn * 32;
#pragma unroll
    for (int mf = 0; mf < 4; ++mf) {
#pragma unroll
        for (int nf = 0; nf < 4; ++nf) {
            int r = m0 + mf * 16 + (lane >> 2);
            int cg = n0 + nf * 8 + (lane & 3) * 2;
            float v0 = acc[mf][nf][0], v1 = acc[mf][nf][1];
            float v2 = acc[mf][nf][2], v3 = acc[mf][nf][3];
            if (bias) {
                float b0 = bias[cg], b1v = bias[cg + 1];
                v0 += b0; v1 += b1v; v2 += b0; v3 += b1v;
            }
            if (EPI == 1) {
                v0 = fmaxf(v0, 0.f); v1 = fmaxf(v1, 0.f);
                v2 = fmaxf(v2, 0.f); v3 = fmaxf(v3, 0.f);
                __nv_bfloat162 hA = __floats2bfloat162_rn(v0, v1);
                __nv_bfloat162 hB = __floats2bfloat162_rn(v2, v3);
                __nv_bfloat162 lA = __floats2bfloat162_rn(v0 - __bfloat162float(hA.x),
                                                          v1 - __bfloat162float(hA.y));
                __nv_bfloat162 lB = __floats2bfloat162_rn(v2 - __bfloat162float(hB.x),
                                                          v3 - __bfloat162float(hB.y));
                *(__nv_bfloat162*)(Chi + (size_t)r * N + cg) = hA;
                *(__nv_bfloat162*)(Clo + (size_t)r * N + cg) = lA;
                *(__nv_bfloat162*)(Chi + (size_t)(r + 8) * N + cg) = hB;
                *(__nv_bfloat162*)(Clo + (size_t)(r + 8) * N + cg) = lB;
            } else {
                size_t o0 = (size_t)r * N + cg, o1 = (size_t)(r + 8) * N + cg;
                if (res) {
                    float2 r0 = *(const float2*)(res + o0);
                    float2 r1 = *(const float2*)(res + o1);
                    v0 += r0.x; v1 += r0.y; v2 += r1.x; v3 += r1.y;
                }
                *(float2*)(C + o0) = make_float2(v0, v1);
                *(float2*)(C + o1) = make_float2(v2, v3);
            }
        }
    }
}

// ---------------- launcher ----------------
extern "C" void kernel_launch(void* const* d_in, const int* in_sizes, int n_in,
                              void* d_out, int out_size) {
    const float* x     = (const float*)d_in[0];
    const float* ln1_w = (const float*)d_in[1];
    const float* ln1_b = (const float*)d_in[2];
    const float* Wq    = (const float*)d_in[3];
    const float* Wk    = (const float*)d_in[4];
    const float* Wv    = (const float*)d_in[5];
    const float* Wo    = (const float*)d_in[6];
    const float* Wo_b  = (const float*)d_in[7];
    const float* ln2_w = (const float*)d_in[8];
    const float* ln2_b = (const float*)d_in[9];
    const float* W1    = (const float*)d_in[10];
    const float* b1    = (const float*)d_in[11];
    const float* W2    = (const float*)d_in[12];
    const float* b2    = (const float*)d_in[13];
    float* out = (float*)d_out;

    float *qkv, *x2;
    __nv_bfloat16 *hh, *hl, *ch, *cl, *uh, *ul;
    __nv_bfloat16 *bqh, *bql, *boh, *bol, *b1h, *b1l, *b2h, *b2l;
    cudaGetSymbolAddress((void**)&qkv, g_qkv);
    cudaGetSymbolAddress((void**)&x2,  g_x2);
    cudaGetSymbolAddress((void**)&hh,  g_hh);
    cudaGetSymbolAddress((void**)&hl,  g_hl);
    cudaGetSymbolAddress((void**)&ch,  g_ch);
    cudaGetSymbolAddress((void**)&cl,  g_cl);
    cudaGetSymbolAddress((void**)&uh,  g_uh);
    cudaGetSymbolAddress((void**)&ul,  g_ul);
    cudaGetSymbolAddress((void**)&bqh, g_bqkv_hi);
    cudaGetSymbolAddress((void**)&bql, g_bqkv_lo);
    cudaGetSymbolAddress((void**)&boh, g_bo_hi);
    cudaGetSymbolAddress((void**)&bol, g_bo_lo);
    cudaGetSymbolAddress((void**)&b1h, g_b1_hi);
    cudaGetSymbolAddress((void**)&b1l, g_b1_lo);
    cudaGetSymbolAddress((void**)&b2h, g_b2_hi);
    cudaGetSymbolAddress((void**)&b2l, g_b2_lo);

    cudaFuncSetAttribute(mma_gemm<0>, cudaFuncAttributeMaxDynamicSharedMemorySize, GSMEM);
    cudaFuncSetAttribute(mma_gemm<1>, cudaFuncAttributeMaxDynamicSharedMemorySize, GSMEM);

    // pack weights
    pack_qkv_bf<<<(QKVC * DMODEL + 255) / 256, 256>>>(Wq, Wk, Wv, bqh, bql);
    pack_noT_bf<<<(DMODEL * DMODEL + 255) / 256, 256>>>(Wo, boh, bol, DMODEL * DMODEL);
    pack_T_bf<<<(DMODEL * DFF + 255) / 256, 256>>>(W1, b1h, b1l, DMODEL, DFF);
    pack_T_bf<<<(DFF * DMODEL + 255) / 256, 256>>>(W2, b2h, b2l, DFF, DMODEL);

    // LN1 -> hi/lo
    ln_split<<<NTOK / 8, 256>>>(x, ln1_w, ln1_b, hh, hl);
    // qkv = h @ Wqkv  (fp32 out)
    mma_gemm<0><<<dim3(QKVC / 128, NTOK / 128), 256, GSMEM>>>(
        hh, hl, bqh, bql, nullptr, nullptr, qkv, nullptr, nullptr, NTOK, QKVC, DMODEL);
    // attention -> ctx hi/lo
    attn_kernel<<<(NB * NH) / 4, 128>>>(qkv, ch, cl);
    // x2 = x + ctx @ Wo^T + Wo_b
    mma_gemm<0><<<dim3(DMODEL / 128, NTOK / 128), 256, GSMEM>>>(
        ch, cl, boh, bol, Wo_b, x, x2, nullptr, nullptr, NTOK, DMODEL, DMODEL);
    // LN2 -> hi/lo
    ln_split<<<NTOK / 8, 256>>>(x2, ln2_w, ln2_b, hh, hl);
    // u = relu(h2 @ W1 + b1) -> bf16 hi/lo
    mma_gemm<1><<<dim3(DFF / 128, NTOK / 128), 256, GSMEM>>>(
        hh, hl, b1h, b1l, b1, nullptr, nullptr, uh, ul, NTOK, DFF, DMODEL);
    // out = x2 + u @ W2 + b2
    mma_gemm<0><<<dim3(DMODEL / 128, NTOK / 128), 256, GSMEM>>>(
        uh, ul, b2h, b2l, b2, x2, out, nullptr, nullptr, NTOK, DMODEL, DFF);
}

// round 8
// speedup vs baseline: 4.2814x; 1.3865x over previous
#include <cuda_runtime.h>
#include <cuda_fp16.h>
#include <cstdint>
#include <math.h>

#define NTOK 81920
#define DMODEL 512
#define DFF 2048
#define NH 8
#define HD 64
#define CTXT 20
#define NB 4096
#define QKVC 1536

// ---------------- scratch ----------------
__device__ float g_qkv[(size_t)NTOK * QKVC];
__device__ float g_x2[(size_t)NTOK * DMODEL];
__device__ __half g_hh[(size_t)NTOK * DMODEL], g_hl[(size_t)NTOK * DMODEL];
__device__ __half g_ch[(size_t)NTOK * DMODEL], g_cl[(size_t)NTOK * DMODEL];
__device__ __half g_uh[(size_t)NTOK * DFF],    g_ul[(size_t)NTOK * DFF];
// packed weights: [N][K] fp16 (hi only; 2-pass compensates activations)
__device__ __half g_bqkv[QKVC * DMODEL];
__device__ __half g_bo[DMODEL * DMODEL];
__device__ __half g_b1w[DFF * DMODEL];
__device__ __half g_b2w[DMODEL * DFF];

// ---------------- helpers ----------------
__device__ __forceinline__ uint32_t smem_to_u32(const void* p) {
    uint32_t a;
    asm("{ .reg .u64 t; cvta.to.shared.u64 t, %1; cvt.u32.u64 %0, t; }" : "=r"(a) : "l"(p));
    return a;
}
#define CP_ASYNC16(dst, src) \
    asm volatile("cp.async.cg.shared.global [%0], [%1], 16;" :: "r"(dst), "l"(src))
#define CP_COMMIT() asm volatile("cp.async.commit_group;")
#define CP_WAIT1()  asm volatile("cp.async.wait_group 1;")

__device__ __forceinline__ void ldsm4(uint32_t& r0, uint32_t& r1, uint32_t& r2, uint32_t& r3,
                                      uint32_t addr) {
    asm volatile("ldmatrix.sync.aligned.m8n8.x4.shared.b16 {%0,%1,%2,%3}, [%4];"
                 : "=r"(r0), "=r"(r1), "=r"(r2), "=r"(r3) : "r"(addr));
}
__device__ __forceinline__ void mma16816(float* c, uint32_t a0, uint32_t a1, uint32_t a2,
                                         uint32_t a3, uint32_t b0, uint32_t b1) {
    asm volatile(
        "mma.sync.aligned.m16n8k16.row.col.f32.f16.f16.f32 "
        "{%0,%1,%2,%3}, {%4,%5,%6,%7}, {%8,%9}, {%0,%1,%2,%3};"
        : "+f"(c[0]), "+f"(c[1]), "+f"(c[2]), "+f"(c[3])
        : "r"(a0), "r"(a1), "r"(a2), "r"(a3), "r"(b0), "r"(b1));
}

// ---------------- weight packing (fp16) ----------------
__global__ void pack_qkv_hf(const float* __restrict__ Wq, const float* __restrict__ Wk,
                            const float* __restrict__ Wv, __half* __restrict__ hi) {
    int i = blockIdx.x * blockDim.x + threadIdx.x;
    if (i >= QKVC * DMODEL) return;
    int n = i >> 9, k = i & 511;
    int sec = n >> 9, h = (n >> 6) & 7, e = n & 63;
    const float* W = (sec == 0) ? Wq : (sec == 1 ? Wk : Wv);
    hi[i] = __float2half(W[((size_t)h * DMODEL + k) * HD + e]);
}
__global__ void pack_T_hf(const float* __restrict__ W, __half* __restrict__ hi, int K, int N) {
    int i = blockIdx.x * blockDim.x + threadIdx.x;
    if (i >= K * N) return;
    int n = i / K, k = i - n * K;
    hi[i] = __float2half(W[(size_t)k * N + n]);
}
__global__ void pack_noT_hf(const float* __restrict__ W, __half* __restrict__ hi, int total) {
    int i = blockIdx.x * blockDim.x + threadIdx.x;
    if (i >= total) return;
    hi[i] = __float2half(W[i]);
}

// ---------------- layernorm -> fp16 hi/lo ----------------
__global__ void ln_split(const float* __restrict__ x, const float* __restrict__ w,
                         const float* __restrict__ b, __half* __restrict__ hi,
                         __half* __restrict__ lo) {
    int gw = (blockIdx.x * blockDim.x + threadIdx.x) >> 5;
    int lane = threadIdx.x & 31;
    if (gw >= NTOK) return;
    const float4* xp = (const float4*)(x + (size_t)gw * DMODEL);
    float4 v[4];
    float s = 0.f, s2 = 0.f;
#pragma unroll
    for (int i = 0; i < 4; i++) {
        v[i] = xp[lane + 32 * i];
        s  += v[i].x + v[i].y + v[i].z + v[i].w;
        s2 += v[i].x * v[i].x + v[i].y * v[i].y + v[i].z * v[i].z + v[i].w * v[i].w;
    }
#pragma unroll
    for (int o = 16; o > 0; o >>= 1) {
        s  += __shfl_xor_sync(0xffffffffu, s,  o);
        s2 += __shfl_xor_sync(0xffffffffu, s2, o);
    }
    float mean = s * (1.f / DMODEL);
    float var  = s2 * (1.f / DMODEL) - mean * mean;
    float rs = rsqrtf(var + 1e-5f);
    const float4* wp = (const float4*)w;
    const float4* bp = (const float4*)b;
#pragma unroll
    for (int i = 0; i < 4; i++) {
        int idx = lane + 32 * i;
        float4 wv = wp[idx], bv = bp[idx], r;
        r.x = (v[i].x - mean) * rs * wv.x + bv.x;
        r.y = (v[i].y - mean) * rs * wv.y + bv.y;
        r.z = (v[i].z - mean) * rs * wv.z + bv.z;
        r.w = (v[i].w - mean) * rs * wv.w + bv.w;
        __half2 h01 = __floats2half2_rn(r.x, r.y);
        __half2 h23 = __floats2half2_rn(r.z, r.w);
        __half2 l01 = __floats2half2_rn(r.x - __half2float(__low2half(h01)),
                                        r.y - __half2float(__high2half(h01)));
        __half2 l23 = __floats2half2_rn(r.z - __half2float(__low2half(h23)),
                                        r.w - __half2float(__high2half(h23)));
        size_t off = (size_t)gw * DMODEL + idx * 4;
        uint2 ph, pl;
        ph.x = *reinterpret_cast<uint32_t*>(&h01);
        ph.y = *reinterpret_cast<uint32_t*>(&h23);
        pl.x = *reinterpret_cast<uint32_t*>(&l01);
        pl.y = *reinterpret_cast<uint32_t*>(&l23);
        *(uint2*)(hi + off) = ph;
        *(uint2*)(lo + off) = pl;
    }
}

// ---------------- attention -> ctx fp16 hi/lo ----------------
__global__ void attn_kernel(const float* __restrict__ qkv, __half* __restrict__ chi,
                            __half* __restrict__ clo) {
    __shared__ float Ks[4][CTXT * HD];
    __shared__ float Vs[4][CTXT * HD];
    int warp = threadIdx.x >> 5, lane = threadIdx.x & 31;
    int pair = blockIdx.x * 4 + warp;
    int b = pair >> 3, h = pair & 7;
    const float* base = qkv + (size_t)b * CTXT * QKVC + h * HD;
    for (int i = lane; i < CTXT * (HD / 4); i += 32) {
        int t = i >> 4, c = (i & 15) << 2;
        float4 kk = *(const float4*)(base + (size_t)t * QKVC + 512 + c);
        float4 vv = *(const float4*)(base + (size_t)t * QKVC + 1024 + c);
        *(float4*)&Ks[warp][t * HD + c] = kk;
        *(float4*)&Vs[warp][t * HD + c] = vv;
    }
    __syncwarp();
    float q[HD];
    int t = lane;
    if (t < CTXT) {
#pragma unroll
        for (int c = 0; c < HD; c += 4) {
            float4 qq = *(const float4*)(base + (size_t)t * QKVC + c);
            q[c] = qq.x; q[c + 1] = qq.y; q[c + 2] = qq.z; q[c + 3] = qq.w;
        }
    } else {
#pragma unroll
        for (int c = 0; c < HD; c++) q[c] = 0.f;
    }
    float S[CTXT];
#pragma unroll
    for (int s = 0; s < CTXT; s++) {
        float acc = 0.f;
#pragma unroll
        for (int c = 0; c < HD; c++) acc = fmaf(q[c], Ks[warp][s * HD + c], acc);
        S[s] = (s <= t) ? acc * 0.125f : -1e30f;
    }
    float m = -1e30f;
#pragma unroll
    for (int s = 0; s < CTXT; s++) m = fmaxf(m, S[s]);
    float sum = 0.f;
#pragma unroll
    for (int s = 0; s < CTXT; s++) { S[s] = __expf(S[s] - m); sum += S[s]; }
    float inv = 1.f / sum;
    float o[HD];
#pragma unroll
    for (int c = 0; c < HD; c++) o[c] = 0.f;
#pragma unroll
    for (int s = 0; s < CTXT; s++) {
        float p = S[s] * inv;
#pragma unroll
        for (int c = 0; c < HD; c++) o[c] = fmaf(p, Vs[warp][s * HD + c], o[c]);
    }
    if (t < CTXT) {
        size_t off = (size_t)(b * CTXT + t) * DMODEL + h * HD;
#pragma unroll
        for (int c = 0; c < HD; c += 4) {
            __half2 h01 = __floats2half2_rn(o[c], o[c + 1]);
            __half2 h23 = __floats2half2_rn(o[c + 2], o[c + 3]);
            __half2 l01 = __floats2half2_rn(o[c] - __half2float(__low2half(h01)),
                                            o[c + 1] - __half2float(__high2half(h01)));
            __half2 l23 = __floats2half2_rn(o[c + 2] - __half2float(__low2half(h23)),
                                            o[c + 3] - __half2float(__high2half(h23)));
            uint2 ph, pl;
            ph.x = *reinterpret_cast<uint32_t*>(&h01);
            ph.y = *reinterpret_cast<uint32_t*>(&h23);
            pl.x = *reinterpret_cast<uint32_t*>(&l01);
            pl.y = *reinterpret_cast<uint32_t*>(&l23);
            *(uint2*)(chi + off + c) = ph;
            *(uint2*)(clo + off + c) = pl;
        }
    }
}

// ---------------- mma.sync fp16x2 GEMM: C[M,N] = (Ah+Al)[M,K] @ B[N,K]^T ----------------
// 128x128 CTA tile, BK=32, 3-stage cp.async, 8 warps of 64x32.
// Stage layout (24KB): Ahi[128][32] @0, Alo @8192, B @16384.
// Swizzle: byte = r*64 + ((c ^ ((r>>1)&3))<<4), c = 16B-chunk index 0..3.
#define STAGE_B 24576
#define GSMEM (3 * STAGE_B)

template <int EPI>  // 0: fp32 out (+bias?,+res?);  1: relu(acc+bias) -> fp16 hi/lo out
__global__ void __launch_bounds__(256, 2)
mma_gemm(const __half* __restrict__ Ahi, const __half* __restrict__ Alo,
         const __half* __restrict__ Bh, const float* __restrict__ bias,
         const float* __restrict__ res, float* __restrict__ C,
         __half* __restrict__ Chi, __half* __restrict__ Clo, int M, int N, int K) {
    extern __shared__ __align__(128) char smem[];
    uint32_t sb = smem_to_u32(smem);
    int tid = threadIdx.x, lane = tid & 31, wid = tid >> 5;
    int row0 = blockIdx.y * 128, col0 = blockIdx.x * 128;
    int wm = wid & 1, wn = wid >> 1;

    // cp.async chunk assignments (6 chunks / thread / stage)
    uint32_t dstOff[6];
    const __half* gsrc[6];
#pragma unroll
    for (int it = 0; it < 6; ++it) {
        int idx = ((it & 1) << 8) + tid;        // 0..511 within region
        int r = idx >> 2, c = idx & 3;
        int region = it >> 1;                   // 0 Ahi, 1 Alo, 2 B
        dstOff[it] = region * 8192 + r * 64 + ((c ^ ((r >> 1) & 3)) << 4);
        const __half* base = (region == 0) ? Ahi : (region == 1) ? Alo : Bh;
        int rowg = ((region < 2) ? row0 : col0) + r;
        gsrc[it] = base + (size_t)rowg * K + c * 8;
    }

    // ldmatrix base addresses (stage 0; add stage offset per iter)
    uint32_t aB[2], bB[2];
    {
        int ra = wm * 64 + (lane & 15);
        int rb = wn * 32 + (lane & 7) + ((lane >> 4) << 3);
#pragma unroll
        for (int kc = 0; kc < 2; ++kc) {
            int ca = kc * 2 + (lane >> 4);
            aB[kc] = sb + ra * 64 + ((ca ^ ((ra >> 1) & 3)) << 4);
            int cb = kc * 2 + ((lane >> 3) & 1);
            bB[kc] = sb + 16384 + rb * 64 + ((cb ^ ((rb >> 1) & 3)) << 4);
        }
    }

    float acc[4][4][4];
#pragma unroll
    for (int i = 0; i < 4; i++)
#pragma unroll
        for (int j = 0; j < 4; j++)
#pragma unroll
            for (int k = 0; k < 4; k++) acc[i][j][k] = 0.f;

    const int T = K >> 5;
    // prologue: stages 0,1
#pragma unroll
    for (int it = 0; it < 6; ++it) CP_ASYNC16(sb + dstOff[it], gsrc[it]);
    CP_COMMIT();
#pragma unroll
    for (int it = 0; it < 6; ++it) CP_ASYNC16(sb + STAGE_B + dstOff[it], gsrc[it] + 32);
    CP_COMMIT();

    for (int t = 0; t < T; ++t) {
        CP_WAIT1();
        __syncthreads();
        if (t + 2 < T) {
            int s2 = (t + 2) % 3;
            size_t ko = (size_t)(t + 2) * 32;
#pragma unroll
            for (int it = 0; it < 6; ++it)
                CP_ASYNC16(sb + s2 * STAGE_B + dstOff[it], gsrc[it] + ko);
        }
        CP_COMMIT();

        uint32_t so = (uint32_t)(t % 3) * STAGE_B;
#pragma unroll
        for (int kc = 0; kc < 2; ++kc) {
            uint32_t aA = aB[kc] + so, bA = bB[kc] + so;
            uint32_t aR[16], bR[8];
            // A hi + B
#pragma unroll
            for (int mf = 0; mf < 4; ++mf)
                ldsm4(aR[mf * 4], aR[mf * 4 + 1], aR[mf * 4 + 2], aR[mf * 4 + 3],
                      aA + mf * 1024);
            ldsm4(bR[0], bR[1], bR[2], bR[3], bA);
            ldsm4(bR[4], bR[5], bR[6], bR[7], bA + 1024);
#pragma unroll
            for (int mf = 0; mf < 4; ++mf)
#pragma unroll
                for (int nf = 0; nf < 4; ++nf)
                    mma16816(acc[mf][nf], aR[mf * 4], aR[mf * 4 + 1], aR[mf * 4 + 2],
                             aR[mf * 4 + 3], bR[(nf >> 1) * 4 + (nf & 1) * 2],
                             bR[(nf >> 1) * 4 + (nf & 1) * 2 + 1]);
            // A lo x B (reuse bR)
#pragma unroll
            for (int mf = 0; mf < 4; ++mf)
                ldsm4(aR[mf * 4], aR[mf * 4 + 1], aR[mf * 4 + 2], aR[mf * 4 + 3],
                      aA + 8192 + mf * 1024);
#pragma unroll
            for (int mf = 0; mf < 4; ++mf)
#pragma unroll
                for (int nf = 0; nf < 4; ++nf)
                    mma16816(acc[mf][nf], aR[mf * 4], aR[mf * 4 + 1], aR[mf * 4 + 2],
                             aR[mf * 4 + 3], bR[(nf >> 1) * 4 + (nf & 1) * 2],
                             bR[(nf >> 1) * 4 + (nf & 1) * 2 + 1]);
        }
    }

    // epilogue
    int m0 = row0 + wm * 64, n0 = col0 + wn * 32;
#pragma unroll
    for (int mf = 0; mf < 4; ++mf) {
#pragma unroll
        for (int nf = 0; nf < 4; ++nf) {
            int r = m0 + mf * 16 + (lane >> 2);
            int cg = n0 + nf * 8 + (lane & 3) * 2;
            float v0 = acc[mf][nf][0], v1 = acc[mf][nf][1];
            float v2 = acc[mf][nf][2], v3 = acc[mf][nf][3];
            if (bias) {
                float b0 = bias[cg], b1v = bias[cg + 1];
                v0 += b0; v1 += b1v; v2 += b0; v3 += b1v;
            }
            if (EPI == 1) {
                v0 = fmaxf(v0, 0.f); v1 = fmaxf(v1, 0.f);
                v2 = fmaxf(v2, 0.f); v3 = fmaxf(v3, 0.f);
                __half2 hA = __floats2half2_rn(v0, v1);
                __half2 hB = __floats2half2_rn(v2, v3);
                __half2 lA = __floats2half2_rn(v0 - __half2float(__low2half(hA)),
                                               v1 - __half2float(__high2half(hA)));
                __half2 lB = __floats2half2_rn(v2 - __half2float(__low2half(hB)),
                                               v3 - __half2float(__high2half(hB)));
                *(__half2*)(Chi + (size_t)r * N + cg) = hA;
                *(__half2*)(Clo + (size_t)r * N + cg) = lA;
                *(__half2*)(Chi + (size_t)(r + 8) * N + cg) = hB;
                *(__half2*)(Clo + (size_t)(r + 8) * N + cg) = lB;
            } else {
                size_t o0 = (size_t)r * N + cg, o1 = (size_t)(r + 8) * N + cg;
                if (res) {
                    float2 r0 = *(const float2*)(res + o0);
                    float2 r1 = *(const float2*)(res + o1);
                    v0 += r0.x; v1 += r0.y; v2 += r1.x; v3 += r1.y;
                }
                *(float2*)(C + o0) = make_float2(v0, v1);
                *(float2*)(C + o1) = make_float2(v2, v3);
            }
        }
    }
}

// ---------------- launcher ----------------
extern "C" void kernel_launch(void* const* d_in, const int* in_sizes, int n_in,
                              void* d_out, int out_size) {
    const float* x     = (const float*)d_in[0];
    const float* ln1_w = (const float*)d_in[1];
    const float* ln1_b = (const float*)d_in[2];
    const float* Wq    = (const float*)d_in[3];
    const float* Wk    = (const float*)d_in[4];
    const float* Wv    = (const float*)d_in[5];
    const float* Wo    = (const float*)d_in[6];
    const float* Wo_b  = (const float*)d_in[7];
    const float* ln2_w = (const float*)d_in[8];
    const float* ln2_b = (const float*)d_in[9];
    const float* W1    = (const float*)d_in[10];
    const float* b1    = (const float*)d_in[11];
    const float* W2    = (const float*)d_in[12];
    const float* b2    = (const float*)d_in[13];
    float* out = (float*)d_out;

    float *qkv, *x2;
    __half *hh, *hl, *ch, *cl, *uh, *ul, *bq, *bo, *b1w, *b2w;
    cudaGetSymbolAddress((void**)&qkv, g_qkv);
    cudaGetSymbolAddress((void**)&x2,  g_x2);
    cudaGetSymbolAddress((void**)&hh,  g_hh);
    cudaGetSymbolAddress((void**)&hl,  g_hl);
    cudaGetSymbolAddress((void**)&ch,  g_ch);
    cudaGetSymbolAddress((void**)&cl,  g_cl);
    cudaGetSymbolAddress((void**)&uh,  g_uh);
    cudaGetSymbolAddress((void**)&ul,  g_ul);
    cudaGetSymbolAddress((void**)&bq,  g_bqkv);
    cudaGetSymbolAddress((void**)&bo,  g_bo);
    cudaGetSymbolAddress((void**)&b1w, g_b1w);
    cudaGetSymbolAddress((void**)&b2w, g_b2w);

    cudaFuncSetAttribute(mma_gemm<0>, cudaFuncAttributeMaxDynamicSharedMemorySize, GSMEM);
    cudaFuncSetAttribute(mma_gemm<1>, cudaFuncAttributeMaxDynamicSharedMemorySize, GSMEM);

    // pack weights (fp16)
    pack_qkv_hf<<<(QKVC * DMODEL + 255) / 256, 256>>>(Wq, Wk, Wv, bq);
    pack_noT_hf<<<(DMODEL * DMODEL + 255) / 256, 256>>>(Wo, bo, DMODEL * DMODEL);
    pack_T_hf<<<(DMODEL * DFF + 255) / 256, 256>>>(W1, b1w, DMODEL, DFF);
    pack_T_hf<<<(DFF * DMODEL + 255) / 256, 256>>>(W2, b2w, DFF, DMODEL);

    // LN1 -> hi/lo
    ln_split<<<NTOK / 8, 256>>>(x, ln1_w, ln1_b, hh, hl);
    // qkv = h @ Wqkv  (fp32 out)
    mma_gemm<0><<<dim3(QKVC / 128, NTOK / 128), 256, GSMEM>>>(
        hh, hl, bq, nullptr, nullptr, qkv, nullptr, nullptr, NTOK, QKVC, DMODEL);
    // attention -> ctx hi/lo
    attn_kernel<<<(NB * NH) / 4, 128>>>(qkv, ch, cl);
    // x2 = x + ctx @ Wo^T + Wo_b
    mma_gemm<0><<<dim3(DMODEL / 128, NTOK / 128), 256, GSMEM>>>(
        ch, cl, bo, Wo_b, x, x2, nullptr, nullptr, NTOK, DMODEL, DMODEL);
    // LN2 -> hi/lo
    ln_split<<<NTOK / 8, 256>>>(x2, ln2_w, ln2_b, hh, hl);
    // u = relu(h2 @ W1 + b1) -> fp16 hi/lo
    mma_gemm<1><<<dim3(DFF / 128, NTOK / 128), 256, GSMEM>>>(
        hh, hl, b1w, b1, nullptr, nullptr, uh, ul, NTOK, DFF, DMODEL);
    // out = x2 + u @ W2 + b2
    mma_gemm<0><<<dim3(DMODEL / 128, NTOK / 128), 256, GSMEM>>>(
        uh, ul, b2w, b2, x2, out, nullptr, nullptr, NTOK, DMODEL, DFF);
}

// round 10
// speedup vs baseline: 5.3110x; 1.2405x over previous
#include <cuda_runtime.h>
#include <cuda_fp16.h>
#include <cstdint>
#include <math.h>

#define NTOK 81920
#define DMODEL 512
#define DFF 2048
#define NH 8
#define HD 64
#define CTXT 20
#define NB 4096
#define QKVC 1536

// ---------------- scratch ----------------
__device__ __half g_qkvh[(size_t)NTOK * QKVC];
__device__ float g_x2[(size_t)NTOK * DMODEL];
__device__ __half g_hh[(size_t)NTOK * DMODEL];
__device__ __half g_ch[(size_t)NTOK * DMODEL], g_cl[(size_t)NTOK * DMODEL];
__device__ __half g_uh[(size_t)NTOK * DFF],    g_ul[(size_t)NTOK * DFF];
// packed weights: [N][K] fp16
__device__ __half g_bqkv[QKVC * DMODEL];
__device__ __half g_bo[DMODEL * DMODEL];
__device__ __half g_b1w[DFF * DMODEL];
__device__ __half g_b2w[DMODEL * DFF];

// ---------------- helpers ----------------
__device__ __forceinline__ uint32_t smem_to_u32(const void* p) {
    uint32_t a;
    asm("{ .reg .u64 t; cvta.to.shared.u64 t, %1; cvt.u32.u64 %0, t; }" : "=r"(a) : "l"(p));
    return a;
}
#define CP_ASYNC16(dst, src) \
    asm volatile("cp.async.cg.shared.global [%0], [%1], 16;" :: "r"(dst), "l"(src))
#define CP_COMMIT() asm volatile("cp.async.commit_group;")
#define CP_WAIT1()  asm volatile("cp.async.wait_group 1;")

__device__ __forceinline__ void ldsm4(uint32_t& r0, uint32_t& r1, uint32_t& r2, uint32_t& r3,
                                      uint32_t addr) {
    asm volatile("ldmatrix.sync.aligned.m8n8.x4.shared.b16 {%0,%1,%2,%3}, [%4];"
                 : "=r"(r0), "=r"(r1), "=r"(r2), "=r"(r3) : "r"(addr));
}
__device__ __forceinline__ void mma16816(float* c, uint32_t a0, uint32_t a1, uint32_t a2,
                                         uint32_t a3, uint32_t b0, uint32_t b1) {
    asm volatile(
        "mma.sync.aligned.m16n8k16.row.col.f32.f16.f16.f32 "
        "{%0,%1,%2,%3}, {%4,%5,%6,%7}, {%8,%9}, {%0,%1,%2,%3};"
        : "+f"(c[0]), "+f"(c[1]), "+f"(c[2]), "+f"(c[3])
        : "r"(a0), "r"(a1), "r"(a2), "r"(a3), "r"(b0), "r"(b1));
}

// ---------------- weight packing (fp16) ----------------
__global__ void pack_qkv_hf(const float* __restrict__ Wq, const float* __restrict__ Wk,
                            const float* __restrict__ Wv, __half* __restrict__ hi) {
    int i = blockIdx.x * blockDim.x + threadIdx.x;
    if (i >= QKVC * DMODEL) return;
    int n = i >> 9, k = i & 511;
    int sec = n >> 9, h = (n >> 6) & 7, e = n & 63;
    const float* W = (sec == 0) ? Wq : (sec == 1 ? Wk : Wv);
    hi[i] = __float2half(W[((size_t)h * DMODEL + k) * HD + e]);
}
__global__ void pack_T_hf(const float* __restrict__ W, __half* __restrict__ hi, int K, int N) {
    int i = blockIdx.x * blockDim.x + threadIdx.x;
    if (i >= K * N) return;
    int n = i / K, k = i - n * K;
    hi[i] = __float2half(W[(size_t)k * N + n]);
}
__global__ void pack_noT_hf(const float* __restrict__ W, __half* __restrict__ hi, int total) {
    int i = blockIdx.x * blockDim.x + threadIdx.x;
    if (i >= total) return;
    hi[i] = __float2half(W[i]);
}

// ---------------- layernorm -> fp16 (hi only; consumers are single-pass GEMMs) ------
__global__ void ln_half(const float* __restrict__ x, const float* __restrict__ w,
                        const float* __restrict__ b, __half* __restrict__ hi) {
    int gw = (blockIdx.x * blockDim.x + threadIdx.x) >> 5;
    int lane = threadIdx.x & 31;
    if (gw >= NTOK) return;
    const float4* xp = (const float4*)(x + (size_t)gw * DMODEL);
    float4 v[4];
    float s = 0.f, s2 = 0.f;
#pragma unroll
    for (int i = 0; i < 4; i++) {
        v[i] = xp[lane + 32 * i];
        s  += v[i].x + v[i].y + v[i].z + v[i].w;
        s2 += v[i].x * v[i].x + v[i].y * v[i].y + v[i].z * v[i].z + v[i].w * v[i].w;
    }
#pragma unroll
    for (int o = 16; o > 0; o >>= 1) {
        s  += __shfl_xor_sync(0xffffffffu, s,  o);
        s2 += __shfl_xor_sync(0xffffffffu, s2, o);
    }
    float mean = s * (1.f / DMODEL);
    float var  = s2 * (1.f / DMODEL) - mean * mean;
    float rs = rsqrtf(var + 1e-5f);
    const float4* wp = (const float4*)w;
    const float4* bp = (const float4*)b;
#pragma unroll
    for (int i = 0; i < 4; i++) {
        int idx = lane + 32 * i;
        float4 wv = wp[idx], bv = bp[idx], r;
        r.x = (v[i].x - mean) * rs * wv.x + bv.x;
        r.y = (v[i].y - mean) * rs * wv.y + bv.y;
        r.z = (v[i].z - mean) * rs * wv.z + bv.z;
        r.w = (v[i].w - mean) * rs * wv.w + bv.w;
        __half2 h01 = __floats2half2_rn(r.x, r.y);
        __half2 h23 = __floats2half2_rn(r.z, r.w);
        uint2 ph;
        ph.x = *reinterpret_cast<uint32_t*>(&h01);
        ph.y = *reinterpret_cast<uint32_t*>(&h23);
        *(uint2*)(hi + (size_t)gw * DMODEL + idx * 4) = ph;
    }
}

// ---------------- attention: fp16 qkv in -> ctx fp16 hi/lo ----------------
__global__ void attn_kernel(const __half* __restrict__ qkv, __half* __restrict__ chi,
                            __half* __restrict__ clo) {
    __shared__ float Ks[4][CTXT * HD];
    __shared__ float Vs[4][CTXT * HD];
    int warp = threadIdx.x >> 5, lane = threadIdx.x & 31;
    int pair = blockIdx.x * 4 + warp;
    int b = pair >> 3, h = pair & 7;
    const __half* base = qkv + (size_t)b * CTXT * QKVC + h * HD;
    for (int i = lane; i < CTXT * (HD / 4); i += 32) {
        int t = i >> 4, c = (i & 15) << 2;
        uint2 kk = *(const uint2*)(base + (size_t)t * QKVC + 512 + c);
        uint2 vv = *(const uint2*)(base + (size_t)t * QKVC + 1024 + c);
        float2 k0 = __half22float2(*(__half2*)&kk.x), k1 = __half22float2(*(__half2*)&kk.y);
        float2 v0 = __half22float2(*(__half2*)&vv.x), v1 = __half22float2(*(__half2*)&vv.y);
        *(float4*)&Ks[warp][t * HD + c] = make_float4(k0.x, k0.y, k1.x, k1.y);
        *(float4*)&Vs[warp][t * HD + c] = make_float4(v0.x, v0.y, v1.x, v1.y);
    }
    __syncwarp();
    float q[HD];
    int t = lane;
    if (t < CTXT) {
#pragma unroll
        for (int c = 0; c < HD; c += 4) {
            uint2 qq = *(const uint2*)(base + (size_t)t * QKVC + c);
            float2 q0 = __half22float2(*(__half2*)&qq.x), q1 = __half22float2(*(__half2*)&qq.y);
            q[c] = q0.x; q[c + 1] = q0.y; q[c + 2] = q1.x; q[c + 3] = q1.y;
        }
    } else {
#pragma unroll
        for (int c = 0; c < HD; c++) q[c] = 0.f;
    }
    float S[CTXT];
#pragma unroll
    for (int s = 0; s < CTXT; s++) {
        float acc = 0.f;
#pragma unroll
        for (int c = 0; c < HD; c++) acc = fmaf(q[c], Ks[warp][s * HD + c], acc);
        S[s] = (s <= t) ? acc * 0.125f : -1e30f;
    }
    float m = -1e30f;
#pragma unroll
    for (int s = 0; s < CTXT; s++) m = fmaxf(m, S[s]);
    float sum = 0.f;
#pragma unroll
    for (int s = 0; s < CTXT; s++) { S[s] = __expf(S[s] - m); sum += S[s]; }
    float inv = 1.f / sum;
    float o[HD];
#pragma unroll
    for (int c = 0; c < HD; c++) o[c] = 0.f;
#pragma unroll
    for (int s = 0; s < CTXT; s++) {
        float p = S[s] * inv;
#pragma unroll
        for (int c = 0; c < HD; c++) o[c] = fmaf(p, Vs[warp][s * HD + c], o[c]);
    }
    if (t < CTXT) {
        size_t off = (size_t)(b * CTXT + t) * DMODEL + h * HD;
#pragma unroll
        for (int c = 0; c < HD; c += 4) {
            __half2 h01 = __floats2half2_rn(o[c], o[c + 1]);
            __half2 h23 = __floats2half2_rn(o[c + 2], o[c + 3]);
            __half2 l01 = __floats2half2_rn(o[c] - __half2float(__low2half(h01)),
                                            o[c + 1] - __half2float(__high2half(h01)));
            __half2 l23 = __floats2half2_rn(o[c + 2] - __half2float(__low2half(h23)),
                                            o[c + 3] - __half2float(__high2half(h23)));
            uint2 ph, pl;
            ph.x = *reinterpret_cast<uint32_t*>(&h01);
            ph.y = *reinterpret_cast<uint32_t*>(&h23);
            pl.x = *reinterpret_cast<uint32_t*>(&l01);
            pl.y = *reinterpret_cast<uint32_t*>(&l23);
            *(uint2*)(chi + off + c) = ph;
            *(uint2*)(clo + off + c) = pl;
        }
    }
}

// ---------------- mma.sync GEMM: C[M,N] = A[M,K] @ B[N,K]^T ----------------
// PASSES=2: A = Ahi + Alo (compensated). PASSES=1: A = Ahi only.
// 128x128 CTA tile, BK=32, 3-stage cp.async, 8 warps of 64x32.
// Stage: Ahi @0, [Alo @8192 if 2-pass], B @8192*(PASSES).
// Swizzle: byte = r*64 + ((c ^ ((r>>1)&3))<<4), c = 16B-chunk index 0..3.
// EPI: 0 = fp32 out (+bias?,+res?); 1 = relu(acc+bias) -> fp16 hi/lo; 2 = plain fp16 out.

template <int PASSES, int EPI>
__global__ void __launch_bounds__(256, 2)
mma_gemm(const __half* __restrict__ Ahi, const __half* __restrict__ Alo,
         const __half* __restrict__ Bh, const float* __restrict__ bias,
         const float* __restrict__ res, float* __restrict__ C,
         __half* __restrict__ Chi, __half* __restrict__ Clo, int M, int N, int K) {
    constexpr int NCHUNK = (PASSES == 2) ? 6 : 4;
    constexpr uint32_t STAGE = (PASSES == 2) ? 24576u : 16384u;
    constexpr uint32_t BOFF = 8192u * PASSES;

    extern __shared__ __align__(128) char smem[];
    uint32_t sb = smem_to_u32(smem);
    int tid = threadIdx.x, lane = tid & 31, wid = tid >> 5;
    int row0 = blockIdx.y * 128, col0 = blockIdx.x * 128;
    int wm = wid & 1, wn = wid >> 1;

    // cp.async chunk assignments
    uint32_t dstOff[NCHUNK];
    const __half* gsrc[NCHUNK];
#pragma unroll
    for (int it = 0; it < NCHUNK; ++it) {
        int idx = ((it & 1) << 8) + tid;        // 0..511 within region
        int r = idx >> 2, c = idx & 3;
        int region = it >> 1;                   // 0 Ahi, [1 Alo,] last B
        dstOff[it] = region * 8192 + r * 64 + ((c ^ ((r >> 1) & 3)) << 4);
        const __half* base;
        bool isB;
        if (PASSES == 2) { base = (region == 0) ? Ahi : (region == 1) ? Alo : Bh; isB = (region == 2); }
        else             { base = (region == 0) ? Ahi : Bh; isB = (region == 1); }
        int rowg = (isB ? col0 : row0) + r;
        gsrc[it] = base + (size_t)rowg * K + c * 8;
    }

    // ldmatrix base addresses (stage 0; add stage offset per iter)
    uint32_t aB[2], bB[2];
    {
        int ra = wm * 64 + (lane & 15);
        int rb = wn * 32 + (lane & 7) + ((lane >> 4) << 3);
#pragma unroll
        for (int kc = 0; kc < 2; ++kc) {
            int ca = kc * 2 + (lane >> 4);
            aB[kc] = sb + ra * 64 + ((ca ^ ((ra >> 1) & 3)) << 4);
            int cb = kc * 2 + ((lane >> 3) & 1);
            bB[kc] = sb + BOFF + rb * 64 + ((cb ^ ((rb >> 1) & 3)) << 4);
        }
    }

    float acc[4][4][4];
#pragma unroll
    for (int i = 0; i < 4; i++)
#pragma unroll
        for (int j = 0; j < 4; j++)
#pragma unroll
            for (int k = 0; k < 4; k++) acc[i][j][k] = 0.f;

    const int T = K >> 5;
    // prologue: stages 0,1
#pragma unroll
    for (int it = 0; it < NCHUNK; ++it) CP_ASYNC16(sb + dstOff[it], gsrc[it]);
    CP_COMMIT();
#pragma unroll
    for (int it = 0; it < NCHUNK; ++it) CP_ASYNC16(sb + STAGE + dstOff[it], gsrc[it] + 32);
    CP_COMMIT();

    for (int t = 0; t < T; ++t) {
        CP_WAIT1();
        __syncthreads();
        if (t + 2 < T) {
            int s2 = (t + 2) % 3;
            size_t ko = (size_t)(t + 2) * 32;
#pragma unroll
            for (int it = 0; it < NCHUNK; ++it)
                CP_ASYNC16(sb + s2 * STAGE + dstOff[it], gsrc[it] + ko);
        }
        CP_COMMIT();

        uint32_t so = (uint32_t)(t % 3) * STAGE;
#pragma unroll
        for (int kc = 0; kc < 2; ++kc) {
            uint32_t aA = aB[kc] + so, bA = bB[kc] + so;
            uint32_t aR[16], bR[8];
            // A hi + B
#pragma unroll
            for (int mf = 0; mf < 4; ++mf)
                ldsm4(aR[mf * 4], aR[mf * 4 + 1], aR[mf * 4 + 2], aR[mf * 4 + 3],
                      aA + mf * 1024);
            ldsm4(bR[0], bR[1], bR[2], bR[3], bA);
            ldsm4(bR[4], bR[5], bR[6], bR[7], bA + 1024);
#pragma unroll
            for (int mf = 0; mf < 4; ++mf)
#pragma unroll
                for (int nf = 0; nf < 4; ++nf)
                    mma16816(acc[mf][nf], aR[mf * 4], aR[mf * 4 + 1], aR[mf * 4 + 2],
                             aR[mf * 4 + 3], bR[(nf >> 1) * 4 + (nf & 1) * 2],
                             bR[(nf >> 1) * 4 + (nf & 1) * 2 + 1]);
            if (PASSES == 2) {
                // A lo x B (reuse bR)
#pragma unroll
                for (int mf = 0; mf < 4; ++mf)
                    ldsm4(aR[mf * 4], aR[mf * 4 + 1], aR[mf * 4 + 2], aR[mf * 4 + 3],
                          aA + 8192 + mf * 1024);
#pragma unroll
                for (int mf = 0; mf < 4; ++mf)
#pragma unroll
                    for (int nf = 0; nf < 4; ++nf)
                        mma16816(acc[mf][nf], aR[mf * 4], aR[mf * 4 + 1], aR[mf * 4 + 2],
                                 aR[mf * 4 + 3], bR[(nf >> 1) * 4 + (nf & 1) * 2],
                                 bR[(nf >> 1) * 4 + (nf & 1) * 2 + 1]);
            }
        }
    }

    // epilogue
    int m0 = row0 + wm * 64, n0 = col0 + wn * 32;
#pragma unroll
    for (int mf = 0; mf < 4; ++mf) {
#pragma unroll
        for (int nf = 0; nf < 4; ++nf) {
            int r = m0 + mf * 16 + (lane >> 2);
            int cg = n0 + nf * 8 + (lane & 3) * 2;
            float v0 = acc[mf][nf][0], v1 = acc[mf][nf][1];
            float v2 = acc[mf][nf][2], v3 = acc[mf][nf][3];
            if (bias) {
                float b0 = bias[cg], b1v = bias[cg + 1];
                v0 += b0; v1 += b1v; v2 += b0; v3 += b1v;
            }
            if (EPI == 1) {
                v0 = fmaxf(v0, 0.f); v1 = fmaxf(v1, 0.f);
                v2 = fmaxf(v2, 0.f); v3 = fmaxf(v3, 0.f);
                __half2 hA = __floats2half2_rn(v0, v1);
                __half2 hB = __floats2half2_rn(v2, v3);
                __half2 lA = __floats2half2_rn(v0 - __half2float(__low2half(hA)),
                                               v1 - __half2float(__high2half(hA)));
                __half2 lB = __floats2half2_rn(v2 - __half2float(__low2half(hB)),
                                               v3 - __half2float(__high2half(hB)));
                *(__half2*)(Chi + (size_t)r * N + cg) = hA;
                *(__half2*)(Clo + (size_t)r * N + cg) = lA;
                *(__half2*)(Chi + (size_t)(r + 8) * N + cg) = hB;
                *(__half2*)(Clo + (size_t)(r + 8) * N + cg) = lB;
            } else if (EPI == 2) {
                *(__half2*)(Chi + (size_t)r * N + cg) = __floats2half2_rn(v0, v1);
                *(__half2*)(Chi + (size_t)(r + 8) * N + cg) = __floats2half2_rn(v2, v3);
            } else {
                size_t o0 = (size_t)r * N + cg, o1 = (size_t)(r + 8) * N + cg;
                if (res) {
                    float2 r0 = *(const float2*)(res + o0);
                    float2 r1 = *(const float2*)(res + o1);
                    v0 += r0.x; v1 += r0.y; v2 += r1.x; v3 += r1.y;
                }
                *(float2*)(C + o0) = make_float2(v0, v1);
                *(float2*)(C + o1) = make_float2(v2, v3);
            }
        }
    }
}

#define SMEM1 (3 * 16384)
#define SMEM2 (3 * 24576)

// ---------------- launcher ----------------
extern "C" void kernel_launch(void* const* d_in, const int* in_sizes, int n_in,
                              void* d_out, int out_size) {
    const float* x     = (const float*)d_in[0];
    const float* ln1_w = (const float*)d_in[1];
    const float* ln1_b = (const float*)d_in[2];
    const float* Wq    = (const float*)d_in[3];
    const float* Wk    = (const float*)d_in[4];
    const float* Wv    = (const float*)d_in[5];
    const float* Wo    = (const float*)d_in[6];
    const float* Wo_b  = (const float*)d_in[7];
    const float* ln2_w = (const float*)d_in[8];
    const float* ln2_b = (const float*)d_in[9];
    const float* W1    = (const float*)d_in[10];
    const float* b1    = (const float*)d_in[11];
    const float* W2    = (const float*)d_in[12];
    const float* b2    = (const float*)d_in[13];
    float* out = (float*)d_out;

    float* x2;
    __half *qkvh, *hh, *ch, *cl, *uh, *ul, *bq, *bo, *b1w, *b2w;
    cudaGetSymbolAddress((void**)&qkvh, g_qkvh);
    cudaGetSymbolAddress((void**)&x2,   g_x2);
    cudaGetSymbolAddress((void**)&hh,   g_hh);
    cudaGetSymbolAddress((void**)&ch,   g_ch);
    cudaGetSymbolAddress((void**)&cl,   g_cl);
    cudaGetSymbolAddress((void**)&uh,   g_uh);
    cudaGetSymbolAddress((void**)&ul,   g_ul);
    cudaGetSymbolAddress((void**)&bq,   g_bqkv);
    cudaGetSymbolAddress((void**)&bo,   g_bo);
    cudaGetSymbolAddress((void**)&b1w,  g_b1w);
    cudaGetSymbolAddress((void**)&b2w,  g_b2w);

    cudaFuncSetAttribute(mma_gemm<1, 2>, cudaFuncAttributeMaxDynamicSharedMemorySize, SMEM1);
    cudaFuncSetAttribute(mma_gemm<1, 1>, cudaFuncAttributeMaxDynamicSharedMemorySize, SMEM1);
    cudaFuncSetAttribute(mma_gemm<2, 0>, cudaFuncAttributeMaxDynamicSharedMemorySize, SMEM2);

    // pack weights (fp16)
    pack_qkv_hf<<<(QKVC * DMODEL + 255) / 256, 256>>>(Wq, Wk, Wv, bq);
    pack_noT_hf<<<(DMODEL * DMODEL + 255) / 256, 256>>>(Wo, bo, DMODEL * DMODEL);
    pack_T_hf<<<(DMODEL * DFF + 255) / 256, 256>>>(W1, b1w, DMODEL, DFF);
    pack_T_hf<<<(DFF * DMODEL + 255) / 256, 256>>>(W2, b2w, DFF, DMODEL);

    // LN1 -> fp16
    ln_half<<<NTOK / 8, 256>>>(x, ln1_w, ln1_b, hh);
    // qkv = h @ Wqkv   (single-pass, fp16 out)
    mma_gemm<1, 2><<<dim3(QKVC / 128, NTOK / 128), 256, SMEM1>>>(
        hh, nullptr, bq, nullptr, nullptr, nullptr, qkvh, nullptr, NTOK, QKVC, DMODEL);
    // attention -> ctx hi/lo
    attn_kernel<<<(NB * NH) / 4, 128>>>(qkvh, ch, cl);
    // x2 = x + ctx @ Wo^T + Wo_b   (2-pass)
    mma_gemm<2, 0><<<dim3(DMODEL / 128, NTOK / 128), 256, SMEM2>>>(
        ch, cl, bo, Wo_b, x, x2, nullptr, nullptr, NTOK, DMODEL, DMODEL);
    // LN2 -> fp16
    ln_half<<<NTOK / 8, 256>>>(x2, ln2_w, ln2_b, hh);
    // u = relu(h2 @ W1 + b1) -> fp16 hi/lo   (single-pass)
    mma_gemm<1, 1><<<dim3(DFF / 128, NTOK / 128), 256, SMEM1>>>(
        hh, nullptr, b1w, b1, nullptr, nullptr, uh, ul, NTOK, DFF, DMODEL);
    // out = x2 + u @ W2 + b2   (2-pass)
    mma_gemm<2, 0><<<dim3(DMODEL / 128, NTOK / 128), 256, SMEM2>>>(
        uh, ul, b2w, b2, x2, out, nullptr, nullptr, NTOK, DMODEL, DFF);
}

// round 12
// speedup vs baseline: 6.8456x; 1.2890x over previous
#include <cuda_runtime.h>
#include <cuda_fp16.h>
#include <cstdint>
#include <math.h>

#define NTOK 81920
#define DMODEL 512
#define DFF 2048
#define NH 8
#define HD 64
#define CTXT 20
#define NB 4096
#define QKVC 1536

// ---------------- scratch ----------------
__device__ __half g_qkvh[(size_t)NTOK * QKVC];
__device__ float g_x2[(size_t)NTOK * DMODEL];
__device__ __half g_hh[(size_t)NTOK * DMODEL];
__device__ __half g_ch[(size_t)NTOK * DMODEL];
__device__ __half g_uh[(size_t)NTOK * DFF];
// packed weights: [N][K] fp16
__device__ __half g_bqkv[QKVC * DMODEL];
__device__ __half g_bo[DMODEL * DMODEL];
__device__ __half g_b1w[DFF * DMODEL];
__device__ __half g_b2w[DMODEL * DFF];

// ---------------- helpers ----------------
__device__ __forceinline__ uint32_t smem_to_u32(const void* p) {
    uint32_t a;
    asm("{ .reg .u64 t; cvta.to.shared.u64 t, %1; cvt.u32.u64 %0, t; }" : "=r"(a) : "l"(p));
    return a;
}
#define CP_ASYNC16(dst, src) \
    asm volatile("cp.async.cg.shared.global [%0], [%1], 16;" :: "r"(dst), "l"(src))
#define CP_COMMIT() asm volatile("cp.async.commit_group;")
#define CP_WAIT1()  asm volatile("cp.async.wait_group 1;")

__device__ __forceinline__ void ldsm4(uint32_t& r0, uint32_t& r1, uint32_t& r2, uint32_t& r3,
                                      uint32_t addr) {
    asm volatile("ldmatrix.sync.aligned.m8n8.x4.shared.b16 {%0,%1,%2,%3}, [%4];"
                 : "=r"(r0), "=r"(r1), "=r"(r2), "=r"(r3) : "r"(addr));
}
__device__ __forceinline__ void mma16816(float* c, uint32_t a0, uint32_t a1, uint32_t a2,
                                         uint32_t a3, uint32_t b0, uint32_t b1) {
    asm volatile(
        "mma.sync.aligned.m16n8k16.row.col.f32.f16.f16.f32 "
        "{%0,%1,%2,%3}, {%4,%5,%6,%7}, {%8,%9}, {%0,%1,%2,%3};"
        : "+f"(c[0]), "+f"(c[1]), "+f"(c[2]), "+f"(c[3])
        : "r"(a0), "r"(a1), "r"(a2), "r"(a3), "r"(b0), "r"(b1));
}

// ---------------- weight packing (fp16) ----------------
__global__ void pack_qkv_hf(const float* __restrict__ Wq, const float* __restrict__ Wk,
                            const float* __restrict__ Wv, __half* __restrict__ hi) {
    int i = blockIdx.x * blockDim.x + threadIdx.x;
    if (i >= QKVC * DMODEL) return;
    int n = i >> 9, k = i & 511;
    int sec = n >> 9, h = (n >> 6) & 7, e = n & 63;
    const float* W = (sec == 0) ? Wq : (sec == 1 ? Wk : Wv);
    hi[i] = __float2half(W[((size_t)h * DMODEL + k) * HD + e]);
}
__global__ void pack_T_hf(const float* __restrict__ W, __half* __restrict__ hi, int K, int N) {
    int i = blockIdx.x * blockDim.x + threadIdx.x;
    if (i >= K * N) return;
    int n = i / K, k = i - n * K;
    hi[i] = __float2half(W[(size_t)k * N + n]);
}
__global__ void pack_noT_hf(const float* __restrict__ W, __half* __restrict__ hi, int total) {
    int i = blockIdx.x * blockDim.x + threadIdx.x;
    if (i >= total) return;
    hi[i] = __float2half(W[i]);
}

// ---------------- layernorm -> fp16 ----------------
__global__ void ln_half(const float* __restrict__ x, const float* __restrict__ w,
                        const float* __restrict__ b, __half* __restrict__ hi) {
    int gw = (blockIdx.x * blockDim.x + threadIdx.x) >> 5;
    int lane = threadIdx.x & 31;
    if (gw >= NTOK) return;
    const float4* xp = (const float4*)(x + (size_t)gw * DMODEL);
    float4 v[4];
    float s = 0.f, s2 = 0.f;
#pragma unroll
    for (int i = 0; i < 4; i++) {
        v[i] = xp[lane + 32 * i];
        s  += v[i].x + v[i].y + v[i].z + v[i].w;
        s2 += v[i].x * v[i].x + v[i].y * v[i].y + v[i].z * v[i].z + v[i].w * v[i].w;
    }
#pragma unroll
    for (int o = 16; o > 0; o >>= 1) {
        s  += __shfl_xor_sync(0xffffffffu, s,  o);
        s2 += __shfl_xor_sync(0xffffffffu, s2, o);
    }
    float mean = s * (1.f / DMODEL);
    float var  = s2 * (1.f / DMODEL) - mean * mean;
    float rs = rsqrtf(var + 1e-5f);
    const float4* wp = (const float4*)w;
    const float4* bp = (const float4*)b;
#pragma unroll
    for (int i = 0; i < 4; i++) {
        int idx = lane + 32 * i;
        float4 wv = wp[idx], bv = bp[idx], r;
        r.x = (v[i].x - mean) * rs * wv.x + bv.x;
        r.y = (v[i].y - mean) * rs * wv.y + bv.y;
        r.z = (v[i].z - mean) * rs * wv.z + bv.z;
        r.w = (v[i].w - mean) * rs * wv.w + bv.w;
        __half2 h01 = __floats2half2_rn(r.x, r.y);
        __half2 h23 = __floats2half2_rn(r.z, r.w);
        uint2 ph;
        ph.x = *reinterpret_cast<uint32_t*>(&h01);
        ph.y = *reinterpret_cast<uint32_t*>(&h23);
        *(uint2*)(hi + (size_t)gw * DMODEL + idx * 4) = ph;
    }
}

// ---------------- attention: fp16 qkv in -> ctx fp16 ----------------
__global__ void attn_kernel(const __half* __restrict__ qkv, __half* __restrict__ chi) {
    __shared__ float Ks[4][CTXT * HD];
    __shared__ float Vs[4][CTXT * HD];
    int warp = threadIdx.x >> 5, lane = threadIdx.x & 31;
    int pair = blockIdx.x * 4 + warp;
    int b = pair >> 3, h = pair & 7;
    const __half* base = qkv + (size_t)b * CTXT * QKVC + h * HD;
    for (int i = lane; i < CTXT * (HD / 4); i += 32) {
        int t = i >> 4, c = (i & 15) << 2;
        uint2 kk = *(const uint2*)(base + (size_t)t * QKVC + 512 + c);
        uint2 vv = *(const uint2*)(base + (size_t)t * QKVC + 1024 + c);
        float2 k0 = __half22float2(*(__half2*)&kk.x), k1 = __half22float2(*(__half2*)&kk.y);
        float2 v0 = __half22float2(*(__half2*)&vv.x), v1 = __half22float2(*(__half2*)&vv.y);
        *(float4*)&Ks[warp][t * HD + c] = make_float4(k0.x, k0.y, k1.x, k1.y);
        *(float4*)&Vs[warp][t * HD + c] = make_float4(v0.x, v0.y, v1.x, v1.y);
    }
    __syncwarp();
    float q[HD];
    int t = lane;
    if (t < CTXT) {
#pragma unroll
        for (int c = 0; c < HD; c += 4) {
            uint2 qq = *(const uint2*)(base + (size_t)t * QKVC + c);
            float2 q0 = __half22float2(*(__half2*)&qq.x), q1 = __half22float2(*(__half2*)&qq.y);
            q[c] = q0.x; q[c + 1] = q0.y; q[c + 2] = q1.x; q[c + 3] = q1.y;
        }
    } else {
#pragma unroll
        for (int c = 0; c < HD; c++) q[c] = 0.f;
    }
    float S[CTXT];
#pragma unroll
    for (int s = 0; s < CTXT; s++) {
        float acc = 0.f;
#pragma unroll
        for (int c = 0; c < HD; c++) acc = fmaf(q[c], Ks[warp][s * HD + c], acc);
        S[s] = (s <= t) ? acc * 0.125f : -1e30f;
    }
    float m = -1e30f;
#pragma unroll
    for (int s = 0; s < CTXT; s++) m = fmaxf(m, S[s]);
    float sum = 0.f;
#pragma unroll
    for (int s = 0; s < CTXT; s++) { S[s] = __expf(S[s] - m); sum += S[s]; }
    float inv = 1.f / sum;
    float o[HD];
#pragma unroll
    for (int c = 0; c < HD; c++) o[c] = 0.f;
#pragma unroll
    for (int s = 0; s < CTXT; s++) {
        float p = S[s] * inv;
#pragma unroll
        for (int c = 0; c < HD; c++) o[c] = fmaf(p, Vs[warp][s * HD + c], o[c]);
    }
    if (t < CTXT) {
        size_t off = (size_t)(b * CTXT + t) * DMODEL + h * HD;
#pragma unroll
        for (int c = 0; c < HD; c += 4) {
            __half2 h01 = __floats2half2_rn(o[c], o[c + 1]);
            __half2 h23 = __floats2half2_rn(o[c + 2], o[c + 3]);
            uint2 ph;
            ph.x = *reinterpret_cast<uint32_t*>(&h01);
            ph.y = *reinterpret_cast<uint32_t*>(&h23);
            *(uint2*)(chi + off + c) = ph;
        }
    }
}

// ---------------- mma.sync single-pass fp16 GEMM: C[M,N] = A[M,K] @ B[N,K]^T ------
// 128x128 CTA tile, BK=32, 3-stage cp.async, 8 warps of 64x32.
// Stage (16KB): A[128][32] @0, B @8192.
// Swizzle: byte = r*64 + ((c ^ ((r>>1)&3))<<4), c = 16B-chunk index 0..3.
// EPI: 0 = fp32 out + bias + res; 1 = relu(acc+bias) -> fp16; 2 = plain fp16 out.
#define STAGE 16384u
#define GSMEM (3 * 16384)

template <int EPI>
__global__ void __launch_bounds__(256, 2)
mma_gemm(const __half* __restrict__ Ahi, const __half* __restrict__ Bh,
         const float* __restrict__ bias, const float* __restrict__ res,
         float* __restrict__ C, __half* __restrict__ Chi, int M, int N, int K) {
    extern __shared__ __align__(128) char smem[];
    uint32_t sb = smem_to_u32(smem);
    int tid = threadIdx.x, lane = tid & 31, wid = tid >> 5;
    int row0 = blockIdx.y * 128, col0 = blockIdx.x * 128;
    int wm = wid & 1, wn = wid >> 1;

    // cp.async chunk assignments (4 chunks / thread / stage)
    uint32_t dstOff[4];
    const __half* gsrc[4];
#pragma unroll
    for (int it = 0; it < 4; ++it) {
        int idx = ((it & 1) << 8) + tid;        // 0..511 within region
        int r = idx >> 2, c = idx & 3;
        int region = it >> 1;                   // 0 A, 1 B
        dstOff[it] = region * 8192 + r * 64 + ((c ^ ((r >> 1) & 3)) << 4);
        const __half* base = (region == 0) ? Ahi : Bh;
        int rowg = ((region == 0) ? row0 : col0) + r;
        gsrc[it] = base + (size_t)rowg * K + c * 8;
    }

    // ldmatrix base addresses (stage 0; add stage offset per iter)
    uint32_t aB[2], bB[2];
    {
        int ra = wm * 64 + (lane & 15);
        int rb = wn * 32 + (lane & 7) + ((lane >> 4) << 3);
#pragma unroll
        for (int kc = 0; kc < 2; ++kc) {
            int ca = kc * 2 + (lane >> 4);
            aB[kc] = sb + ra * 64 + ((ca ^ ((ra >> 1) & 3)) << 4);
            int cb = kc * 2 + ((lane >> 3) & 1);
            bB[kc] = sb + 8192 + rb * 64 + ((cb ^ ((rb >> 1) & 3)) << 4);
        }
    }

    float acc[4][4][4];
#pragma unroll
    for (int i = 0; i < 4; i++)
#pragma unroll
        for (int j = 0; j < 4; j++)
#pragma unroll
            for (int k = 0; k < 4; k++) acc[i][j][k] = 0.f;

    const int T = K >> 5;
    // prologue: stages 0,1
#pragma unroll
    for (int it = 0; it < 4; ++it) CP_ASYNC16(sb + dstOff[it], gsrc[it]);
    CP_COMMIT();
#pragma unroll
    for (int it = 0; it < 4; ++it) CP_ASYNC16(sb + STAGE + dstOff[it], gsrc[it] + 32);
    CP_COMMIT();

    for (int t = 0; t < T; ++t) {
        CP_WAIT1();
        __syncthreads();
        if (t + 2 < T) {
            int s2 = (t + 2) % 3;
            size_t ko = (size_t)(t + 2) * 32;
#pragma unroll
            for (int it = 0; it < 4; ++it)
                CP_ASYNC16(sb + s2 * STAGE + dstOff[it], gsrc[it] + ko);
        }
        CP_COMMIT();

        uint32_t so = (uint32_t)(t % 3) * STAGE;
#pragma unroll
        for (int kc = 0; kc < 2; ++kc) {
            uint32_t aA = aB[kc] + so, bA = bB[kc] + so;
            uint32_t aR[16], bR[8];
#pragma unroll
            for (int mf = 0; mf < 4; ++mf)
                ldsm4(aR[mf * 4], aR[mf * 4 + 1], aR[mf * 4 + 2], aR[mf * 4 + 3],
                      aA + mf * 1024);
            ldsm4(bR[0], bR[1], bR[2], bR[3], bA);
            ldsm4(bR[4], bR[5], bR[6], bR[7], bA + 1024);
#pragma unroll
            for (int mf = 0; mf < 4; ++mf)
#pragma unroll
                for (int nf = 0; nf < 4; ++nf)
                    mma16816(acc[mf][nf], aR[mf * 4], aR[mf * 4 + 1], aR[mf * 4 + 2],
                             aR[mf * 4 + 3], bR[(nf >> 1) * 4 + (nf & 1) * 2],
                             bR[(nf >> 1) * 4 + (nf & 1) * 2 + 1]);
        }
    }

    // epilogue
    int m0 = row0 + wm * 64, n0 = col0 + wn * 32;
#pragma unroll
    for (int mf = 0; mf < 4; ++mf) {
#pragma unroll
        for (int nf = 0; nf < 4; ++nf) {
            int r = m0 + mf * 16 + (lane >> 2);
            int cg = n0 + nf * 8 + (lane & 3) * 2;
            float v0 = acc[mf][nf][0], v1 = acc[mf][nf][1];
            float v2 = acc[mf][nf][2], v3 = acc[mf][nf][3];
            if (EPI == 0 || EPI == 1) {
                float b0 = bias[cg], b1v = bias[cg + 1];
                v0 += b0; v1 += b1v; v2 += b0; v3 += b1v;
            }
            if (EPI == 1) {
                v0 = fmaxf(v0, 0.f); v1 = fmaxf(v1, 0.f);
                v2 = fmaxf(v2, 0.f); v3 = fmaxf(v3, 0.f);
                *(__half2*)(Chi + (size_t)r * N + cg) = __floats2half2_rn(v0, v1);
                *(__half2*)(Chi + (size_t)(r + 8) * N + cg) = __floats2half2_rn(v2, v3);
            } else if (EPI == 2) {
                *(__half2*)(Chi + (size_t)r * N + cg) = __floats2half2_rn(v0, v1);
                *(__half2*)(Chi + (size_t)(r + 8) * N + cg) = __floats2half2_rn(v2, v3);
            } else {
                size_t o0 = (size_t)r * N + cg, o1 = (size_t)(r + 8) * N + cg;
                float2 r0 = *(const float2*)(res + o0);
                float2 r1 = *(const float2*)(res + o1);
                v0 += r0.x; v1 += r0.y; v2 += r1.x; v3 += r1.y;
                *(float2*)(C + o0) = make_float2(v0, v1);
                *(float2*)(C + o1) = make_float2(v2, v3);
            }
        }
    }
}

// ---------------- launcher ----------------
extern "C" void kernel_launch(void* const* d_in, const int* in_sizes, int n_in,
                              void* d_out, int out_size) {
    const float* x     = (const float*)d_in[0];
    const float* ln1_w = (const float*)d_in[1];
    const float* ln1_b = (const float*)d_in[2];
    const float* Wq    = (const float*)d_in[3];
    const float* Wk    = (const float*)d_in[4];
    const float* Wv    = (const float*)d_in[5];
    const float* Wo    = (const float*)d_in[6];
    const float* Wo_b  = (const float*)d_in[7];
    const float* ln2_w = (const float*)d_in[8];
    const float* ln2_b = (const float*)d_in[9];
    const float* W1    = (const float*)d_in[10];
    const float* b1    = (const float*)d_in[11];
    const float* W2    = (const float*)d_in[12];
    const float* b2    = (const float*)d_in[13];
    float* out = (float*)d_out;

    float* x2;
    __half *qkvh, *hh, *ch, *uh, *bq, *bo, *b1w, *b2w;
    cudaGetSymbolAddress((void**)&qkvh, g_qkvh);
    cudaGetSymbolAddress((void**)&x2,   g_x2);
    cudaGetSymbolAddress((void**)&hh,   g_hh);
    cudaGetSymbolAddress((void**)&ch,   g_ch);
    cudaGetSymbolAddress((void**)&uh,   g_uh);
    cudaGetSymbolAddress((void**)&bq,   g_bqkv);
    cudaGetSymbolAddress((void**)&bo,   g_bo);
    cudaGetSymbolAddress((void**)&b1w,  g_b1w);
    cudaGetSymbolAddress((void**)&b2w,  g_b2w);

    cudaFuncSetAttribute(mma_gemm<0>, cudaFuncAttributeMaxDynamicSharedMemorySize, GSMEM);
    cudaFuncSetAttribute(mma_gemm<1>, cudaFuncAttributeMaxDynamicSharedMemorySize, GSMEM);
    cudaFuncSetAttribute(mma_gemm<2>, cudaFuncAttributeMaxDynamicSharedMemorySize, GSMEM);

    // pack weights (fp16)
    pack_qkv_hf<<<(QKVC * DMODEL + 255) / 256, 256>>>(Wq, Wk, Wv, bq);
    pack_noT_hf<<<(DMODEL * DMODEL + 255) / 256, 256>>>(Wo, bo, DMODEL * DMODEL);
    pack_T_hf<<<(DMODEL * DFF + 255) / 256, 256>>>(W1, b1w, DMODEL, DFF);
    pack_T_hf<<<(DFF * DMODEL + 255) / 256, 256>>>(W2, b2w, DFF, DMODEL);

    // LN1 -> fp16
    ln_half<<<NTOK / 8, 256>>>(x, ln1_w, ln1_b, hh);
    // qkv = h @ Wqkv   (fp16 out)
    mma_gemm<2><<<dim3(QKVC / 128, NTOK / 128), 256, GSMEM>>>(
        hh, bq, nullptr, nullptr, nullptr, qkvh, NTOK, QKVC, DMODEL);
    // attention -> ctx fp16
    attn_kernel<<<(NB * NH) / 4, 128>>>(qkvh, ch);
    // x2 = x + ctx @ Wo^T + Wo_b
    mma_gemm<0><<<dim3(DMODEL / 128, NTOK / 128), 256, GSMEM>>>(
        ch, bo, Wo_b, x, x2, nullptr, NTOK, DMODEL, DMODEL);
    // LN2 -> fp16
    ln_half<<<NTOK / 8, 256>>>(x2, ln2_w, ln2_b, hh);
    // u = relu(h2 @ W1 + b1) -> fp16
    mma_gemm<1><<<dim3(DFF / 128, NTOK / 128), 256, GSMEM>>>(
        hh, b1w, b1, nullptr, nullptr, uh, NTOK, DFF, DMODEL);
    // out = x2 + u @ W2 + b2
    mma_gemm<0><<<dim3(DMODEL / 128, NTOK / 128), 256, GSMEM>>>(
        uh, b2w, b2, x2, out, nullptr, NTOK, DMODEL, DFF);
}

// round 13
// speedup vs baseline: 6.9371x; 1.0134x over previous
#include <cuda_runtime.h>
#include <cuda_fp16.h>
#include <cstdint>
#include <math.h>

#define NTOK 81920
#define DMODEL 512
#define DFF 2048
#define NH 8
#define HD 64
#define CTXT 20
#define NB 4096
#define QKVC 1536

// ---------------- scratch ----------------
__device__ __half g_qkvh[(size_t)NTOK * QKVC];
__device__ float g_x2[(size_t)NTOK * DMODEL];
__device__ __half g_hh[(size_t)NTOK * DMODEL];
__device__ __half g_ch[(size_t)NTOK * DMODEL];
__device__ __half g_uh[(size_t)NTOK * DFF];
// packed weights: [N][K] fp16
__device__ __half g_bqkv[QKVC * DMODEL];
__device__ __half g_bo[DMODEL * DMODEL];
__device__ __half g_b1w[DFF * DMODEL];
__device__ __half g_b2w[DMODEL * DFF];

// ---------------- helpers ----------------
__device__ __forceinline__ uint32_t smem_to_u32(const void* p) {
    uint32_t a;
    asm("{ .reg .u64 t; cvta.to.shared.u64 t, %1; cvt.u32.u64 %0, t; }" : "=r"(a) : "l"(p));
    return a;
}
#define CP_ASYNC16(dst, src) \
    asm volatile("cp.async.cg.shared.global [%0], [%1], 16;" :: "r"(dst), "l"(src))
#define CP_COMMIT() asm volatile("cp.async.commit_group;")
#define CP_WAIT1()  asm volatile("cp.async.wait_group 1;")

__device__ __forceinline__ void ldsm4(uint32_t& r0, uint32_t& r1, uint32_t& r2, uint32_t& r3,
                                      uint32_t addr) {
    asm volatile("ldmatrix.sync.aligned.m8n8.x4.shared.b16 {%0,%1,%2,%3}, [%4];"
                 : "=r"(r0), "=r"(r1), "=r"(r2), "=r"(r3) : "r"(addr));
}
__device__ __forceinline__ void mma16816(float* c, uint32_t a0, uint32_t a1, uint32_t a2,
                                         uint32_t a3, uint32_t b0, uint32_t b1) {
    asm volatile(
        "mma.sync.aligned.m16n8k16.row.col.f32.f16.f16.f32 "
        "{%0,%1,%2,%3}, {%4,%5,%6,%7}, {%8,%9}, {%0,%1,%2,%3};"
        : "+f"(c[0]), "+f"(c[1]), "+f"(c[2]), "+f"(c[3])
        : "r"(a0), "r"(a1), "r"(a2), "r"(a3), "r"(b0), "r"(b1));
}

// ---------------- weight packing (fp16) ----------------
__global__ void pack_qkv_hf(const float* __restrict__ Wq, const float* __restrict__ Wk,
                            const float* __restrict__ Wv, __half* __restrict__ hi) {
    int i = blockIdx.x * blockDim.x + threadIdx.x;
    if (i >= QKVC * DMODEL) return;
    int n = i >> 9, k = i & 511;
    int sec = n >> 9, h = (n >> 6) & 7, e = n & 63;
    const float* W = (sec == 0) ? Wq : (sec == 1 ? Wk : Wv);
    hi[i] = __float2half(W[((size_t)h * DMODEL + k) * HD + e]);
}
__global__ void pack_T_hf(const float* __restrict__ W, __half* __restrict__ hi, int K, int N) {
    int i = blockIdx.x * blockDim.x + threadIdx.x;
    if (i >= K * N) return;
    int n = i / K, k = i - n * K;
    hi[i] = __float2half(W[(size_t)k * N + n]);
}
__global__ void pack_noT_hf(const float* __restrict__ W, __half* __restrict__ hi, int total) {
    int i = blockIdx.x * blockDim.x + threadIdx.x;
    if (i >= total) return;
    hi[i] = __float2half(W[i]);
}

// ---------------- layernorm -> fp16 ----------------
__global__ void ln_half(const float* __restrict__ x, const float* __restrict__ w,
                        const float* __restrict__ b, __half* __restrict__ hi) {
    int gw = (blockIdx.x * blockDim.x + threadIdx.x) >> 5;
    int lane = threadIdx.x & 31;
    if (gw >= NTOK) return;
    const float4* xp = (const float4*)(x + (size_t)gw * DMODEL);
    float4 v[4];
    float s = 0.f, s2 = 0.f;
#pragma unroll
    for (int i = 0; i < 4; i++) {
        v[i] = xp[lane + 32 * i];
        s  += v[i].x + v[i].y + v[i].z + v[i].w;
        s2 += v[i].x * v[i].x + v[i].y * v[i].y + v[i].z * v[i].z + v[i].w * v[i].w;
    }
#pragma unroll
    for (int o = 16; o > 0; o >>= 1) {
        s  += __shfl_xor_sync(0xffffffffu, s,  o);
        s2 += __shfl_xor_sync(0xffffffffu, s2, o);
    }
    float mean = s * (1.f / DMODEL);
    float var  = s2 * (1.f / DMODEL) - mean * mean;
    float rs = rsqrtf(var + 1e-5f);
    const float4* wp = (const float4*)w;
    const float4* bp = (const float4*)b;
#pragma unroll
    for (int i = 0; i < 4; i++) {
        int idx = lane + 32 * i;
        float4 wv = wp[idx], bv = bp[idx], r;
        r.x = (v[i].x - mean) * rs * wv.x + bv.x;
        r.y = (v[i].y - mean) * rs * wv.y + bv.y;
        r.z = (v[i].z - mean) * rs * wv.z + bv.z;
        r.w = (v[i].w - mean) * rs * wv.w + bv.w;
        __half2 h01 = __floats2half2_rn(r.x, r.y);
        __half2 h23 = __floats2half2_rn(r.z, r.w);
        uint2 ph;
        ph.x = *reinterpret_cast<uint32_t*>(&h01);
        ph.y = *reinterpret_cast<uint32_t*>(&h23);
        *(uint2*)(hi + (size_t)gw * DMODEL + idx * 4) = ph;
    }
}

// ---------------- attention: fp16 K/V smem, low-reg, 2-channel-pass ----------------
__global__ void __launch_bounds__(128, 4)
attn_kernel(const __half* __restrict__ qkv, __half* __restrict__ chi) {
    __shared__ __half Ks[4][CTXT * HD];
    __shared__ __half Vs[4][CTXT * HD];
    int warp = threadIdx.x >> 5, lane = threadIdx.x & 31;
    int pair = blockIdx.x * 4 + warp;
    int b = pair >> 3, h = pair & 7;
    const __half* base = qkv + (size_t)b * CTXT * QKVC + h * HD;
    // cooperative K,V load (stay fp16 — lossless)
    for (int i = lane; i < CTXT * (HD / 4); i += 32) {
        int t = i >> 4, c = (i & 15) << 2;
        *(uint2*)&Ks[warp][t * HD + c] = *(const uint2*)(base + (size_t)t * QKVC + 512 + c);
        *(uint2*)&Vs[warp][t * HD + c] = *(const uint2*)(base + (size_t)t * QKVC + 1024 + c);
    }
    __syncwarp();

    int t = lane;
    uint32_t q2[32];            // q as 32 packed half2
    if (t < CTXT) {
#pragma unroll
        for (int c = 0; c < 16; c++) {
            uint2 qq = *(const uint2*)(base + (size_t)t * QKVC + c * 4);
            q2[c * 2] = qq.x; q2[c * 2 + 1] = qq.y;
        }
    } else {
#pragma unroll
        for (int c = 0; c < 32; c++) q2[c] = 0;
    }

    float S[CTXT];
#pragma unroll
    for (int s = 0; s < CTXT; s++) {
        float acc = 0.f;
#pragma unroll
        for (int c2 = 0; c2 < 32; c2++) {
            float2 kf = __half22float2(*reinterpret_cast<__half2*>(&Ks[warp][s * HD + c2 * 2]));
            float2 qf = __half22float2(*reinterpret_cast<__half2*>(&q2[c2]));
            acc = fmaf(qf.x, kf.x, acc);
            acc = fmaf(qf.y, kf.y, acc);
        }
        S[s] = (s <= t) ? acc * 0.125f : -1e30f;
    }
    float m = -1e30f;
#pragma unroll
    for (int s = 0; s < CTXT; s++) m = fmaxf(m, S[s]);
    float sum = 0.f;
#pragma unroll
    for (int s = 0; s < CTXT; s++) { S[s] = __expf(S[s] - m); sum += S[s]; }
    float inv = 1.f / sum;
#pragma unroll
    for (int s = 0; s < CTXT; s++) S[s] *= inv;

    size_t off = (size_t)(b * CTXT + t) * DMODEL + h * HD;
#pragma unroll
    for (int hp = 0; hp < 2; hp++) {
        float o[32];
#pragma unroll
        for (int c = 0; c < 32; c++) o[c] = 0.f;
#pragma unroll
        for (int s = 0; s < CTXT; s++) {
            float p = S[s];
#pragma unroll
            for (int c2 = 0; c2 < 16; c2++) {
                float2 vf = __half22float2(
                    *reinterpret_cast<__half2*>(&Vs[warp][s * HD + hp * 32 + c2 * 2]));
                o[c2 * 2]     = fmaf(p, vf.x, o[c2 * 2]);
                o[c2 * 2 + 1] = fmaf(p, vf.y, o[c2 * 2 + 1]);
            }
        }
        if (t < CTXT) {
#pragma unroll
            for (int c = 0; c < 32; c += 4) {
                __half2 h01 = __floats2half2_rn(o[c], o[c + 1]);
                __half2 h23 = __floats2half2_rn(o[c + 2], o[c + 3]);
                uint2 ph;
                ph.x = *reinterpret_cast<uint32_t*>(&h01);
                ph.y = *reinterpret_cast<uint32_t*>(&h23);
                *(uint2*)(chi + off + hp * 32 + c) = ph;
            }
        }
    }
}

// ---------------- mma.sync single-pass fp16 GEMM, BK=64: C = A @ B^T ------
// 128x128 CTA tile, BK=64, 3-stage cp.async, 8 warps of 64x32.
// Stage (32KB): A[128][64] @0, B @16384. Rows are 128B: swizzle c^(r&7) on 16B chunks.
// EPI: 0 = fp32 out + bias + res; 1 = relu(acc+bias) -> fp16; 2 = plain fp16 out.
#define STAGE 32768u
#define GSMEM (3 * 32768)

template <int EPI>
__global__ void __launch_bounds__(256, 2)
mma_gemm(const __half* __restrict__ Ahi, const __half* __restrict__ Bh,
         const float* __restrict__ bias, const float* __restrict__ res,
         float* __restrict__ C, __half* __restrict__ Chi, int M, int N, int K) {
    extern __shared__ __align__(128) char smem[];
    uint32_t sb = smem_to_u32(smem);
    int tid = threadIdx.x, lane = tid & 31, wid = tid >> 5;
    int row0 = blockIdx.y * 128, col0 = blockIdx.x * 128;
    int wm = wid & 1, wn = wid >> 1;

    // cp.async: each region (A,B) = 1024 16B-chunks; thread covers 4 per region
    const __half* aBase = Ahi + (size_t)row0 * K;
    const __half* bBase = Bh + (size_t)col0 * K;
    uint32_t dstOff[4], goff[4];
#pragma unroll
    for (int j = 0; j < 4; ++j) {
        int idx = (j << 8) + tid;
        int r = idx >> 3, c = idx & 7;
        dstOff[j] = r * 128 + ((c ^ (r & 7)) << 4);
        goff[j] = (uint32_t)(r * K + c * 8);
    }

    // ldmatrix base addresses (stage 0)
    uint32_t aB4[4], bB4[4];
    {
        int ra = wm * 64 + (lane & 15);
        int rb = wn * 32 + (lane & 7) + ((lane >> 4) << 3);
#pragma unroll
        for (int kc = 0; kc < 4; ++kc) {
            int ca = kc * 2 + (lane >> 4);
            aB4[kc] = sb + ra * 128 + ((ca ^ (ra & 7)) << 4);
            int cb = kc * 2 + ((lane >> 3) & 1);
            bB4[kc] = sb + 16384 + rb * 128 + ((cb ^ (rb & 7)) << 4);
        }
    }

    float acc[4][4][4];
#pragma unroll
    for (int i = 0; i < 4; i++)
#pragma unroll
        for (int j = 0; j < 4; j++)
#pragma unroll
            for (int k = 0; k < 4; k++) acc[i][j][k] = 0.f;

    const int T = K >> 6;
    // prologue: stages 0,1
#pragma unroll
    for (int j = 0; j < 4; ++j) {
        CP_ASYNC16(sb + dstOff[j], aBase + goff[j]);
        CP_ASYNC16(sb + 16384 + dstOff[j], bBase + goff[j]);
    }
    CP_COMMIT();
#pragma unroll
    for (int j = 0; j < 4; ++j) {
        CP_ASYNC16(sb + STAGE + dstOff[j], aBase + 64 + goff[j]);
        CP_ASYNC16(sb + STAGE + 16384 + dstOff[j], bBase + 64 + goff[j]);
    }
    CP_COMMIT();

    for (int t = 0; t < T; ++t) {
        CP_WAIT1();
        __syncthreads();
        if (t + 2 < T) {
            uint32_t so2 = (uint32_t)((t + 2) % 3) * STAGE;
            int ko = (t + 2) * 64;
#pragma unroll
            for (int j = 0; j < 4; ++j) {
                CP_ASYNC16(sb + so2 + dstOff[j], aBase + ko + goff[j]);
                CP_ASYNC16(sb + so2 + 16384 + dstOff[j], bBase + ko + goff[j]);
            }
        }
        CP_COMMIT();

        uint32_t so = (uint32_t)(t % 3) * STAGE;
#pragma unroll
        for (int kc = 0; kc < 4; ++kc) {
            uint32_t aA = aB4[kc] + so, bA = bB4[kc] + so;
            uint32_t aR[16], bR[8];
#pragma unroll
            for (int mf = 0; mf < 4; ++mf)
                ldsm4(aR[mf * 4], aR[mf * 4 + 1], aR[mf * 4 + 2], aR[mf * 4 + 3],
                      aA + mf * 2048);
            ldsm4(bR[0], bR[1], bR[2], bR[3], bA);
            ldsm4(bR[4], bR[5], bR[6], bR[7], bA + 2048);
#pragma unroll
            for (int mf = 0; mf < 4; ++mf)
#pragma unroll
                for (int nf = 0; nf < 4; ++nf)
                    mma16816(acc[mf][nf], aR[mf * 4], aR[mf * 4 + 1], aR[mf * 4 + 2],
                             aR[mf * 4 + 3], bR[(nf >> 1) * 4 + (nf & 1) * 2],
                             bR[(nf >> 1) * 4 + (nf & 1) * 2 + 1]);
        }
    }

    // epilogue
    int m0 = row0 + wm * 64, n0 = col0 + wn * 32;
#pragma unroll
    for (int mf = 0; mf < 4; ++mf) {
#pragma unroll
        for (int nf = 0; nf < 4; ++nf) {
            int r = m0 + mf * 16 + (lane >> 2);
            int cg = n0 + nf * 8 + (lane & 3) * 2;
            float v0 = acc[mf][nf][0], v1 = acc[mf][nf][1];
            float v2 = acc[mf][nf][2], v3 = acc[mf][nf][3];
            if (EPI == 0 || EPI == 1) {
                float b0 = bias[cg], b1v = bias[cg + 1];
                v0 += b0; v1 += b1v; v2 += b0; v3 += b1v;
            }
            if (EPI == 1) {
                v0 = fmaxf(v0, 0.f); v1 = fmaxf(v1, 0.f);
                v2 = fmaxf(v2, 0.f); v3 = fmaxf(v3, 0.f);
                *(__half2*)(Chi + (size_t)r * N + cg) = __floats2half2_rn(v0, v1);
                *(__half2*)(Chi + (size_t)(r + 8) * N + cg) = __floats2half2_rn(v2, v3);
            } else if (EPI == 2) {
                *(__half2*)(Chi + (size_t)r * N + cg) = __floats2half2_rn(v0, v1);
                *(__half2*)(Chi + (size_t)(r + 8) * N + cg) = __floats2half2_rn(v2, v3);
            } else {
                size_t o0 = (size_t)r * N + cg, o1 = (size_t)(r + 8) * N + cg;
                float2 r0 = *(const float2*)(res + o0);
                float2 r1 = *(const float2*)(res + o1);
                v0 += r0.x; v1 += r0.y; v2 += r1.x; v3 += r1.y;
                *(float2*)(C + o0) = make_float2(v0, v1);
                *(float2*)(C + o1) = make_float2(v2, v3);
            }
        }
    }
}

// ---------------- launcher ----------------
extern "C" void kernel_launch(void* const* d_in, const int* in_sizes, int n_in,
                              void* d_out, int out_size) {
    const float* x     = (const float*)d_in[0];
    const float* ln1_w = (const float*)d_in[1];
    const float* ln1_b = (const float*)d_in[2];
    const float* Wq    = (const float*)d_in[3];
    const float* Wk    = (const float*)d_in[4];
    const float* Wv    = (const float*)d_in[5];
    const float* Wo    = (const float*)d_in[6];
    const float* Wo_b  = (const float*)d_in[7];
    const float* ln2_w = (const float*)d_in[8];
    const float* ln2_b = (const float*)d_in[9];
    const float* W1    = (const float*)d_in[10];
    const float* b1    = (const float*)d_in[11];
    const float* W2    = (const float*)d_in[12];
    const float* b2    = (const float*)d_in[13];
    float* out = (float*)d_out;

    float* x2;
    __half *qkvh, *hh, *ch, *uh, *bq, *bo, *b1w, *b2w;
    cudaGetSymbolAddress((void**)&qkvh, g_qkvh);
    cudaGetSymbolAddress((void**)&x2,   g_x2);
    cudaGetSymbolAddress((void**)&hh,   g_hh);
    cudaGetSymbolAddress((void**)&ch,   g_ch);
    cudaGetSymbolAddress((void**)&uh,   g_uh);
    cudaGetSymbolAddress((void**)&bq,   g_bqkv);
    cudaGetSymbolAddress((void**)&bo,   g_bo);
    cudaGetSymbolAddress((void**)&b1w,  g_b1w);
    cudaGetSymbolAddress((void**)&b2w,  g_b2w);

    cudaFuncSetAttribute(mma_gemm<0>, cudaFuncAttributeMaxDynamicSharedMemorySize, GSMEM);
    cudaFuncSetAttribute(mma_gemm<1>, cudaFuncAttributeMaxDynamicSharedMemorySize, GSMEM);
    cudaFuncSetAttribute(mma_gemm<2>, cudaFuncAttributeMaxDynamicSharedMemorySize, GSMEM);

    // pack weights (fp16)
    pack_qkv_hf<<<(QKVC * DMODEL + 255) / 256, 256>>>(Wq, Wk, Wv, bq);
    pack_noT_hf<<<(DMODEL * DMODEL + 255) / 256, 256>>>(Wo, bo, DMODEL * DMODEL);
    pack_T_hf<<<(DMODEL * DFF + 255) / 256, 256>>>(W1, b1w, DMODEL, DFF);
    pack_T_hf<<<(DFF * DMODEL + 255) / 256, 256>>>(W2, b2w, DFF, DMODEL);

    // LN1 -> fp16
    ln_half<<<NTOK / 8, 256>>>(x, ln1_w, ln1_b, hh);
    // qkv = h @ Wqkv   (fp16 out)
    mma_gemm<2><<<dim3(QKVC / 128, NTOK / 128), 256, GSMEM>>>(
        hh, bq, nullptr, nullptr, nullptr, qkvh, NTOK, QKVC, DMODEL);
    // attention -> ctx fp16
    attn_kernel<<<(NB * NH) / 4, 128>>>(qkvh, ch);
    // x2 = x + ctx @ Wo^T + Wo_b
    mma_gemm<0><<<dim3(DMODEL / 128, NTOK / 128), 256, GSMEM>>>(
        ch, bo, Wo_b, x, x2, nullptr, NTOK, DMODEL, DMODEL);
    // LN2 -> fp16
    ln_half<<<NTOK / 8, 256>>>(x2, ln2_w, ln2_b, hh);
    // u = relu(h2 @ W1 + b1) -> fp16
    mma_gemm<1><<<dim3(DFF / 128, NTOK / 128), 256, GSMEM>>>(
        hh, b1w, b1, nullptr, nullptr, uh, NTOK, DFF, DMODEL);
    // out = x2 + u @ W2 + b2
    mma_gemm<0><<<dim3(DMODEL / 128, NTOK / 128), 256, GSMEM>>>(
        uh, b2w, b2, x2, out, nullptr, NTOK, DMODEL, DFF);
}